// round 5
// baseline (speedup 1.0000x reference)
#include <cuda_runtime.h>
#include <cuda_fp16.h>
#include <cstdint>

#define B_  128
#define T_  2048
#define H_  200
#define HP  208          // N padded to 16
#define LD  216          // smem leading dim in halves (432B rows, conflict-free for ldmatrix)
#define G4  800

// ---------------- device scratch ----------------
__device__ __align__(16) half g_Ua[HP * LD];   // Ua fp16, [n][k] row-major, zero-padded
__device__ float g_qadd[B_ * HP];
__device__ float g_hpre[B_ * G4];
__device__ float g_sc[B_ * T_];
__device__ float g_ctx[B_ * H_];

// ---------------- helpers ----------------
__device__ __forceinline__ uint32_t smem_u32(const void* p) {
    uint32_t a;
    asm("{ .reg .u64 t; cvta.to.shared.u64 t, %1; cvt.u32.u64 %0, t; }" : "=r"(a) : "l"(p));
    return a;
}
__device__ __forceinline__ void ldsm4(uint32_t* r, uint32_t addr) {
    asm volatile("ldmatrix.sync.aligned.m8n8.x4.shared.b16 {%0,%1,%2,%3}, [%4];"
                 : "=r"(r[0]), "=r"(r[1]), "=r"(r[2]), "=r"(r[3]) : "r"(addr));
}
__device__ __forceinline__ void mma16816(float* d, const uint32_t* a, uint32_t b0, uint32_t b1) {
    asm volatile("mma.sync.aligned.m16n8k16.row.col.f32.f16.f16.f32 "
                 "{%0,%1,%2,%3}, {%4,%5,%6,%7}, {%8,%9}, {%0,%1,%2,%3};"
                 : "+f"(d[0]), "+f"(d[1]), "+f"(d[2]), "+f"(d[3])
                 : "r"(a[0]), "r"(a[1]), "r"(a[2]), "r"(a[3]), "r"(b0), "r"(b1));
}
__device__ __forceinline__ float tanh_fast(float x) {
    float y;
    asm("tanh.approx.f32 %0, %1;" : "=f"(y) : "f"(x));
    return y;
}
__device__ __forceinline__ float fast_sig(float x) {
    return __fdividef(1.f, 1.f + __expf(-x));
}
__device__ __forceinline__ float ref_tanh(float x) {
    float e = __expf(2.f * x);
    return 1.f - __fdividef(2.f, e + 1.f);
}
__device__ __forceinline__ float wred(float v) {
    v += __shfl_xor_sync(~0u, v, 16); v += __shfl_xor_sync(~0u, v, 8);
    v += __shfl_xor_sync(~0u, v, 4);  v += __shfl_xor_sync(~0u, v, 2);
    v += __shfl_xor_sync(~0u, v, 1);  return v;
}

// -------- prep: Ua -> fp16 [n][LD] row-major, zero-padded --------
__global__ void prep_ua(const float* __restrict__ Ua) {
    int n = blockIdx.x, k = threadIdx.x;
    if (k < LD) {
        float v = (n < H_ && k < H_) ? Ua[n * H_ + k] : 0.f;
        g_Ua[n * LD + k] = __float2half(v);
    }
}

// -------- prep: qadd + h_pre, warp-cooperative coalesced dots --------
__global__ void prep_qh(const float* __restrict__ h0, const float* __restrict__ Wa,
                        const float* __restrict__ ba, const float* __restrict__ bua,
                        const float* __restrict__ Whh, const float* __restrict__ bhh) {
    int b = blockIdx.x, tid = threadIdx.x, wid = tid >> 5, lid = tid & 31;
    __shared__ float hs[H_];
    if (tid < H_) hs[tid] = h0[b * H_ + tid];
    __syncthreads();
    for (int r = wid; r < HP; r += 8) {
        float acc = 0.f;
        if (r < H_) {
            const float* w = Wa + r * H_;
            for (int k = lid; k < H_; k += 32) acc += hs[k] * w[k];
        }
        acc = wred(acc);
        if (lid == 0) g_qadd[b * HP + r] = (r < H_) ? acc + ba[r] + bua[r] : 0.f;
    }
    for (int r = wid; r < G4; r += 8) {
        const float* w = Whh + r * H_;
        float acc = 0.f;
        for (int k = lid; k < H_; k += 32) acc += hs[k] * w[k];
        acc = wred(acc);
        if (lid == 0) g_hpre[b * G4 + r] = acc + bhh[r];
    }
}

// -------- fused scores via raw mma.sync, max chain parallelism --------
#define SM_AS   0
#define SM_BS   (128 * LD * 2)                   // 55296
#define SM_QV   (SM_BS + HP * LD * 2)            // 145152
#define SM_SP   (SM_QV + HP * 8)                 // 146816  partial scores [2][128]
#define SM_TOT  (SM_SP + 256 * 4)                // 147840

__global__ void __launch_bounds__(512) scores_k(const float* __restrict__ enc,
                                                const float* __restrict__ Va,
                                                const float* __restrict__ bva) {
    extern __shared__ char sm[];
    half*   As = (half*)(sm + SM_AS);
    half*   Bs = (half*)(sm + SM_BS);
    float2* qv = (float2*)(sm + SM_QV);
    float*  sp = (float*)(sm + SM_SP);

    int tid = threadIdx.x, wid = tid >> 5, lid = tid & 31;
    int b  = blockIdx.x >> 4;
    int t0 = (blockIdx.x & 15) << 7;

    {
        const uint4* s4 = (const uint4*)g_Ua;
        uint4* d4 = (uint4*)Bs;
        for (int i = tid; i < (HP * LD * 2) / 16; i += 512) d4[i] = s4[i];
    }
    if (tid < HP) qv[tid] = make_float2(g_qadd[b * HP + tid], (tid < H_) ? Va[tid] : 0.f);

    const float* encb = enc + (size_t)(b * T_ + t0) * H_;
    for (int u = tid; u < 128 * 27; u += 512) {
        int row = u / 27, oc = u % 27, k = oc * 8;
        uint4 v;
        half2* hp = (half2*)&v;
        if (k < H_) {
            const float4 f0 = *(const float4*)(encb + row * H_ + k);
            const float4 f1 = *(const float4*)(encb + row * H_ + k + 4);
            hp[0] = __floats2half2_rn(f0.x, f0.y);
            hp[1] = __floats2half2_rn(f0.z, f0.w);
            hp[2] = __floats2half2_rn(f1.x, f1.y);
            hp[3] = __floats2half2_rn(f1.z, f1.w);
        } else {
            v = make_uint4(0, 0, 0, 0);
        }
        *(uint4*)(As + row * LD + k) = v;
    }
    __syncthreads();

    int rg = wid & 7, nh = wid >> 3;
    int lr = lid & 7, quad = lid >> 3;
    uint32_t a_base = smem_u32(As) + (uint32_t)(((rg * 16) + (quad & 1) * 8 + lr) * LD + (quad >> 1) * 8) * 2u;
    uint32_t b_base = smem_u32(Bs) + (uint32_t)((((quad >> 1) * 8) + lr) * LD + (quad & 1) * 8) * 2u;

    uint32_t afr[13][4];
    #pragma unroll
    for (int s = 0; s < 13; s++) ldsm4(afr[s], a_base + (uint32_t)(s * 32));

    float pA = 0.f, pB = 0.f;
    int cq = (lid & 3) * 2;
    int p0 = nh ? 7 : 0, p1 = nh ? 13 : 7;

    int p = p0;
    for (; p + 1 < p1; p += 2) {
        float acc[8][4];
        #pragma unroll
        for (int i = 0; i < 8; i++)
            #pragma unroll
            for (int j = 0; j < 4; j++) acc[i][j] = 0.f;
        uint32_t bpA = b_base + (uint32_t)(p * 16 * LD * 2);
        uint32_t bpB = bpA + (uint32_t)(16 * LD * 2);
        #pragma unroll
        for (int s = 0; s < 13; s++) {
            int o = (s < 6) ? 0 : 4;
            uint32_t ba_[4], bb_[4];
            ldsm4(ba_, bpA + (uint32_t)(s * 32));
            ldsm4(bb_, bpB + (uint32_t)(s * 32));
            mma16816(acc[o + 0], afr[s], ba_[0], ba_[1]);
            mma16816(acc[o + 1], afr[s], ba_[2], ba_[3]);
            mma16816(acc[o + 2], afr[s], bb_[0], bb_[1]);
            mma16816(acc[o + 3], afr[s], bb_[2], bb_[3]);
        }
        #pragma unroll
        for (int t = 0; t < 2; t++) {
            int n0 = (p + t) * 16 + cq;
            float2 q0 = qv[n0],     q1 = qv[n0 + 1];
            float2 q2 = qv[n0 + 8], q3 = qv[n0 + 9];
            float* cL = acc[t * 2];
            float* cLk = acc[t * 2 + 4];
            float* cH = acc[t * 2 + 1];
            float* cHk = acc[t * 2 + 5];
            pA += q0.y * tanh_fast(q0.x + cL[0] + cLk[0]);
            pA += q1.y * tanh_fast(q1.x + cL[1] + cLk[1]);
            pB += q0.y * tanh_fast(q0.x + cL[2] + cLk[2]);
            pB += q1.y * tanh_fast(q1.x + cL[3] + cLk[3]);
            pA += q2.y * tanh_fast(q2.x + cH[0] + cHk[0]);
            pA += q3.y * tanh_fast(q3.x + cH[1] + cHk[1]);
            pB += q2.y * tanh_fast(q2.x + cH[2] + cHk[2]);
            pB += q3.y * tanh_fast(q3.x + cH[3] + cHk[3]);
        }
    }
    if (p < p1) {
        float acc[4][4];
        #pragma unroll
        for (int i = 0; i < 4; i++)
            #pragma unroll
            for (int j = 0; j < 4; j++) acc[i][j] = 0.f;
        uint32_t bpA = b_base + (uint32_t)(p * 16 * LD * 2);
        #pragma unroll
        for (int s = 0; s < 13; s++) {
            int o = (s < 6) ? 0 : 2;
            uint32_t ba_[4];
            ldsm4(ba_, bpA + (uint32_t)(s * 32));
            mma16816(acc[o + 0], afr[s], ba_[0], ba_[1]);
            mma16816(acc[o + 1], afr[s], ba_[2], ba_[3]);
        }
        int n0 = p * 16 + cq;
        float2 q0 = qv[n0],     q1 = qv[n0 + 1];
        float2 q2 = qv[n0 + 8], q3 = qv[n0 + 9];
        pA += q0.y * tanh_fast(q0.x + acc[0][0] + acc[2][0]);
        pA += q1.y * tanh_fast(q1.x + acc[0][1] + acc[2][1]);
        pB += q0.y * tanh_fast(q0.x + acc[0][2] + acc[2][2]);
        pB += q1.y * tanh_fast(q1.x + acc[0][3] + acc[2][3]);
        pA += q2.y * tanh_fast(q2.x + acc[1][0] + acc[3][0]);
        pA += q3.y * tanh_fast(q3.x + acc[1][1] + acc[3][1]);
        pB += q2.y * tanh_fast(q2.x + acc[1][2] + acc[3][2]);
        pB += q3.y * tanh_fast(q3.x + acc[1][3] + acc[3][3]);
    }

    pA += __shfl_xor_sync(~0u, pA, 1); pA += __shfl_xor_sync(~0u, pA, 2);
    pB += __shfl_xor_sync(~0u, pB, 1); pB += __shfl_xor_sync(~0u, pB, 2);
    if ((lid & 3) == 0) {
        int r = lid >> 2;
        sp[nh * 128 + rg * 16 + r]     = pA;
        sp[nh * 128 + rg * 16 + r + 8] = pB;
    }
    __syncthreads();
    if (tid < 128)
        g_sc[b * T_ + t0 + tid] = sp[tid] + sp[128 + tid] + bva[0];
}

// -------- fused softmax + context: one block per batch --------
// 512 threads; softmax over T=2048 in smem, then 16 warps each accumulate a
// 128-t slice of context in registers; tree-reduce partials; scale by 1/sum.
__global__ void __launch_bounds__(512) softmax_ctx_k(const float* __restrict__ enc) {
    __shared__ float att[T_];            // 8 KB (unnormalized exp)
    __shared__ float part[16][209];      // 13.4 KB, stride 209 -> conflict-free columns
    __shared__ float redm[16], reds[16], sinv;

    int b = blockIdx.x, tid = threadIdx.x, wid = tid >> 5, lid = tid & 31;

    // max
    float v[4], m = -1e30f;
    #pragma unroll
    for (int i = 0; i < 4; i++) { v[i] = g_sc[b * T_ + tid + i * 512]; m = fmaxf(m, v[i]); }
    #pragma unroll
    for (int s = 16; s; s >>= 1) m = fmaxf(m, __shfl_xor_sync(~0u, m, s));
    if (lid == 0) redm[wid] = m;
    __syncthreads();
    if (tid < 32) {
        float mm = (lid < 16) ? redm[lid] : -1e30f;
        #pragma unroll
        for (int s = 8; s; s >>= 1) mm = fmaxf(mm, __shfl_xor_sync(~0u, mm, s));
        if (lid == 0) redm[0] = mm;
    }
    __syncthreads();
    m = redm[0];

    // exp + sum
    float sum = 0.f;
    #pragma unroll
    for (int i = 0; i < 4; i++) { float e = __expf(v[i] - m); att[tid + i * 512] = e; sum += e; }
    #pragma unroll
    for (int s = 16; s; s >>= 1) sum += __shfl_xor_sync(~0u, sum, s);
    if (lid == 0) reds[wid] = sum;
    __syncthreads();
    if (tid < 32) {
        float ss = (lid < 16) ? reds[lid] : 0.f;
        #pragma unroll
        for (int s = 8; s; s >>= 1) ss += __shfl_xor_sync(~0u, ss, s);
        if (lid == 0) sinv = 1.f / ss;
    }
    __syncthreads();

    // context: warp wid owns t in [wid*128, wid*128+128)
    float acc[7] = {0.f, 0.f, 0.f, 0.f, 0.f, 0.f, 0.f};
    const float* eb = enc + ((size_t)b * T_ + wid * 128) * H_;
    #pragma unroll 2
    for (int t = 0; t < 128; t++) {
        float a = att[wid * 128 + t];
        const float* er = eb + (size_t)t * H_;
        #pragma unroll
        for (int j = 0; j < 6; j++) acc[j] += a * er[lid + 32 * j];
        if (lid < 8) acc[6] += a * er[lid + 192];
    }
    #pragma unroll
    for (int j = 0; j < 7; j++) {
        int h = lid + 32 * j;
        if (h < H_) part[wid][h] = acc[j];
    }
    __syncthreads();
    if (tid < H_) {
        float s2 = 0.f;
        #pragma unroll
        for (int w = 0; w < 16; w++) s2 += part[w][tid];
        g_ctx[b * H_ + tid] = s2 * sinv;
    }
}

// -------- decoder: warp-cooperative coalesced GEMVs + 5 tiny steps --------
__global__ void decoder_k(const float* __restrict__ x,  const float* __restrict__ c0,
                          const float* __restrict__ Wih, const float* __restrict__ bih,
                          const float* __restrict__ W1, const float* __restrict__ b1,
                          const float* __restrict__ W2, const float* __restrict__ b2,
                          const float* __restrict__ W3, const float* __restrict__ b3,
                          float* __restrict__ out) {
    int b = blockIdx.x, tid = threadIdx.x, wid = tid >> 5, lid = tid & 31;
    __shared__ float ctx[H_], gb[G4], wcol[G4], c0s[H_], r0s[H_], l1s[100], l2s[50];
    __shared__ float xs;
    if (tid < H_) {
        ctx[tid] = g_ctx[b * H_ + tid];
        c0s[tid] = c0[b * H_ + tid];
    }
    if (tid == 0) xs = x[b];
    for (int g = tid; g < G4; g += 256) wcol[g] = Wih[g * 201];
    __syncthreads();
    for (int g = wid; g < G4; g += 8) {
        const float* w = Wih + g * 201 + 1;
        float acc = 0.f;
        for (int k = lid; k < H_; k += 32) acc += ctx[k] * w[k];
        acc = wred(acc);
        if (lid == 0) gb[g] = acc + bih[g] + g_hpre[b * G4 + g];
    }
    __syncthreads();
    float xv = xs;
    for (int st = 0; st < 5; st++) {
        if (tid < H_) {
            float gi = gb[tid]          + xv * wcol[tid];
            float gf = gb[H_ + tid]     + xv * wcol[H_ + tid];
            float gg = gb[2 * H_ + tid] + xv * wcol[2 * H_ + tid];
            float go = gb[3 * H_ + tid] + xv * wcol[3 * H_ + tid];
            float c  = fast_sig(gf) * c0s[tid] + fast_sig(gi) * ref_tanh(gg);
            float h  = fast_sig(go) * ref_tanh(c);
            r0s[tid] = fmaxf(h, 0.f);
        }
        __syncthreads();
        for (int r = wid; r < 100; r += 8) {
            const float* w = W1 + r * H_;
            float acc = 0.f;
            for (int k = lid; k < H_; k += 32) acc += r0s[k] * w[k];
            acc = wred(acc);
            if (lid == 0) l1s[r] = fmaxf(acc + b1[r], 0.f);
        }
        __syncthreads();
        for (int r = wid; r < 50; r += 8) {
            const float* w = W2 + r * 100;
            float acc = 0.f;
            for (int k = lid; k < 100; k += 32) acc += l1s[k] * w[k];
            acc = wred(acc);
            if (lid == 0) l2s[r] = fmaxf(acc + b2[r], 0.f);
        }
        __syncthreads();
        if (wid == 0) {
            float acc = 0.f;
            for (int k = lid; k < 50; k += 32) acc += l2s[k] * W3[k];
            acc = wred(acc);
            if (lid == 0) { float y = acc + b3[0]; out[b * 5 + st] = y; xs = y; }
        }
        __syncthreads();
        xv = xs;
    }
}

extern "C" void kernel_launch(void* const* d_in, const int* in_sizes, int n_in,
                              void* d_out, int out_size) {
    const float* x   = (const float*)d_in[0];
    const float* h0  = (const float*)d_in[1];
    const float* c0  = (const float*)d_in[2];
    const float* enc = (const float*)d_in[3];
    const float* Wa  = (const float*)d_in[4];
    const float* ba  = (const float*)d_in[5];
    const float* Ua  = (const float*)d_in[6];
    const float* bua = (const float*)d_in[7];
    const float* Va  = (const float*)d_in[8];
    const float* bva = (const float*)d_in[9];
    const float* Wih = (const float*)d_in[10];
    const float* Whh = (const float*)d_in[11];
    const float* bih = (const float*)d_in[12];
    const float* bhh = (const float*)d_in[13];
    const float* W1  = (const float*)d_in[14];
    const float* b1  = (const float*)d_in[15];
    const float* W2  = (const float*)d_in[16];
    const float* b2  = (const float*)d_in[17];
    const float* W3  = (const float*)d_in[18];
    const float* b3  = (const float*)d_in[19];
    float* out = (float*)d_out;

    prep_ua<<<HP, 256>>>(Ua);                       // launch 1
    prep_qh<<<B_, 256>>>(h0, Wa, ba, bua, Whh, bhh);// launch 2

    cudaFuncSetAttribute(scores_k, cudaFuncAttributeMaxDynamicSharedMemorySize, SM_TOT);
    scores_k<<<B_ * 16, 512, SM_TOT>>>(enc, Va, bva);  // launch 3

    softmax_ctx_k<<<B_, 512>>>(enc);                // launch 4 <- ncu capture slot

    decoder_k<<<B_, 256>>>(x, c0, Wih, bih, W1, b1, W2, b2, W3, b3, out);  // launch 5
}

// round 7
// speedup vs baseline: 2.3383x; 2.3383x over previous
#include <cuda_runtime.h>
#include <cuda_fp16.h>
#include <cstdint>

#define B_  128
#define T_  2048
#define H_  200
#define HP  208          // N padded to 16
#define LD  216          // smem leading dim in halves (432B rows, conflict-free for ldmatrix)
#define G4  800

// ---------------- device scratch ----------------
__device__ __align__(16) half g_Ua[HP * LD];   // Ua fp16, [n][k] row-major, zero-padded
__device__ float g_qadd[B_ * HP];
__device__ float g_hpre[B_ * G4];
__device__ float g_sc[B_ * T_];
__device__ float g_ctx[B_ * H_];

// ---------------- helpers ----------------
__device__ __forceinline__ uint32_t smem_u32(const void* p) {
    uint32_t a;
    asm("{ .reg .u64 t; cvta.to.shared.u64 t, %1; cvt.u32.u64 %0, t; }" : "=r"(a) : "l"(p));
    return a;
}
__device__ __forceinline__ void ldsm4(uint32_t* r, uint32_t addr) {
    asm volatile("ldmatrix.sync.aligned.m8n8.x4.shared.b16 {%0,%1,%2,%3}, [%4];"
                 : "=r"(r[0]), "=r"(r[1]), "=r"(r[2]), "=r"(r[3]) : "r"(addr));
}
__device__ __forceinline__ void mma16816(float* d, const uint32_t* a, uint32_t b0, uint32_t b1) {
    asm volatile("mma.sync.aligned.m16n8k16.row.col.f32.f16.f16.f32 "
                 "{%0,%1,%2,%3}, {%4,%5,%6,%7}, {%8,%9}, {%0,%1,%2,%3};"
                 : "+f"(d[0]), "+f"(d[1]), "+f"(d[2]), "+f"(d[3])
                 : "r"(a[0]), "r"(a[1]), "r"(a[2]), "r"(a[3]), "r"(b0), "r"(b1));
}
__device__ __forceinline__ float tanh_fast(float x) {
    float y;
    asm("tanh.approx.f32 %0, %1;" : "=f"(y) : "f"(x));
    return y;
}
__device__ __forceinline__ float fast_sig(float x) {
    return __fdividef(1.f, 1.f + __expf(-x));
}
__device__ __forceinline__ float ref_tanh(float x) {
    float e = __expf(2.f * x);
    return 1.f - __fdividef(2.f, e + 1.f);
}
__device__ __forceinline__ float wred(float v) {
    v += __shfl_xor_sync(~0u, v, 16); v += __shfl_xor_sync(~0u, v, 8);
    v += __shfl_xor_sync(~0u, v, 4);  v += __shfl_xor_sync(~0u, v, 2);
    v += __shfl_xor_sync(~0u, v, 1);  return v;
}

// -------- prep (merged): blocks 0..207 lay out Ua; blocks 208..335 do qadd+h_pre --------
__global__ void __launch_bounds__(512) prep_k(const float* __restrict__ Ua,
                                              const float* __restrict__ h0,
                                              const float* __restrict__ Wa,
                                              const float* __restrict__ ba,
                                              const float* __restrict__ bua,
                                              const float* __restrict__ Whh,
                                              const float* __restrict__ bhh) {
    int blk = blockIdx.x, tid = threadIdx.x;
    if (blk < HP) {
        int n = blk;
        if (tid < LD) {
            float v = (n < H_ && tid < H_) ? Ua[n * H_ + tid] : 0.f;
            g_Ua[n * LD + tid] = __float2half(v);
        }
        return;
    }
    int b = blk - HP, wid = tid >> 5, lid = tid & 31;
    __shared__ float hs[H_];
    if (tid < H_) hs[tid] = h0[b * H_ + tid];
    __syncthreads();
    for (int r = wid; r < HP; r += 16) {
        float acc = 0.f;
        if (r < H_) {
            const float* w = Wa + r * H_;
            #pragma unroll
            for (int k = lid; k < H_; k += 32) acc += hs[k] * w[k];
        }
        acc = wred(acc);
        if (lid == 0) g_qadd[b * HP + r] = (r < H_) ? acc + ba[r] + bua[r] : 0.f;
    }
    for (int r = wid; r < G4; r += 16) {
        const float* w = Whh + r * H_;
        float acc = 0.f;
        #pragma unroll
        for (int k = lid; k < H_; k += 32) acc += hs[k] * w[k];
        acc = wred(acc);
        if (lid == 0) g_hpre[b * G4 + r] = acc + bhh[r];
    }
}

// -------- fused scores via raw mma.sync, max chain parallelism --------
#define SM_AS   0
#define SM_BS   (128 * LD * 2)                   // 55296
#define SM_QV   (SM_BS + HP * LD * 2)            // 145152
#define SM_SP   (SM_QV + HP * 8)                 // 146816  partial scores [2][128]
#define SM_TOT  (SM_SP + 256 * 4)                // 147840

__global__ void __launch_bounds__(512) scores_k(const float* __restrict__ enc,
                                                const float* __restrict__ Va,
                                                const float* __restrict__ bva) {
    extern __shared__ char sm[];
    half*   As = (half*)(sm + SM_AS);
    half*   Bs = (half*)(sm + SM_BS);
    float2* qv = (float2*)(sm + SM_QV);
    float*  sp = (float*)(sm + SM_SP);

    int tid = threadIdx.x, wid = tid >> 5, lid = tid & 31;
    int b  = blockIdx.x >> 4;
    int t0 = (blockIdx.x & 15) << 7;

    {
        const uint4* s4 = (const uint4*)g_Ua;
        uint4* d4 = (uint4*)Bs;
        for (int i = tid; i < (HP * LD * 2) / 16; i += 512) d4[i] = s4[i];
    }
    if (tid < HP) qv[tid] = make_float2(g_qadd[b * HP + tid], (tid < H_) ? Va[tid] : 0.f);

    const float* encb = enc + (size_t)(b * T_ + t0) * H_;
    for (int u = tid; u < 128 * 27; u += 512) {
        int row = u / 27, oc = u % 27, k = oc * 8;
        uint4 v;
        half2* hp = (half2*)&v;
        if (k < H_) {
            const float4 f0 = *(const float4*)(encb + row * H_ + k);
            const float4 f1 = *(const float4*)(encb + row * H_ + k + 4);
            hp[0] = __floats2half2_rn(f0.x, f0.y);
            hp[1] = __floats2half2_rn(f0.z, f0.w);
            hp[2] = __floats2half2_rn(f1.x, f1.y);
            hp[3] = __floats2half2_rn(f1.z, f1.w);
        } else {
            v = make_uint4(0, 0, 0, 0);
        }
        *(uint4*)(As + row * LD + k) = v;
    }
    __syncthreads();

    int rg = wid & 7, nh = wid >> 3;
    int lr = lid & 7, quad = lid >> 3;
    uint32_t a_base = smem_u32(As) + (uint32_t)(((rg * 16) + (quad & 1) * 8 + lr) * LD + (quad >> 1) * 8) * 2u;
    uint32_t b_base = smem_u32(Bs) + (uint32_t)((((quad >> 1) * 8) + lr) * LD + (quad & 1) * 8) * 2u;

    uint32_t afr[13][4];
    #pragma unroll
    for (int s = 0; s < 13; s++) ldsm4(afr[s], a_base + (uint32_t)(s * 32));

    float pA = 0.f, pB = 0.f;
    int cq = (lid & 3) * 2;
    int p0 = nh ? 7 : 0, p1 = nh ? 13 : 7;

    int p = p0;
    for (; p + 1 < p1; p += 2) {
        float acc[8][4];
        #pragma unroll
        for (int i = 0; i < 8; i++)
            #pragma unroll
            for (int j = 0; j < 4; j++) acc[i][j] = 0.f;
        uint32_t bpA = b_base + (uint32_t)(p * 16 * LD * 2);
        uint32_t bpB = bpA + (uint32_t)(16 * LD * 2);
        #pragma unroll
        for (int s = 0; s < 13; s++) {
            int o = (s < 6) ? 0 : 4;
            uint32_t ba_[4], bb_[4];
            ldsm4(ba_, bpA + (uint32_t)(s * 32));
            ldsm4(bb_, bpB + (uint32_t)(s * 32));
            mma16816(acc[o + 0], afr[s], ba_[0], ba_[1]);
            mma16816(acc[o + 1], afr[s], ba_[2], ba_[3]);
            mma16816(acc[o + 2], afr[s], bb_[0], bb_[1]);
            mma16816(acc[o + 3], afr[s], bb_[2], bb_[3]);
        }
        #pragma unroll
        for (int t = 0; t < 2; t++) {
            int n0 = (p + t) * 16 + cq;
            float2 q0 = qv[n0],     q1 = qv[n0 + 1];
            float2 q2 = qv[n0 + 8], q3 = qv[n0 + 9];
            float* cL = acc[t * 2];
            float* cLk = acc[t * 2 + 4];
            float* cH = acc[t * 2 + 1];
            float* cHk = acc[t * 2 + 5];
            pA += q0.y * tanh_fast(q0.x + cL[0] + cLk[0]);
            pA += q1.y * tanh_fast(q1.x + cL[1] + cLk[1]);
            pB += q0.y * tanh_fast(q0.x + cL[2] + cLk[2]);
            pB += q1.y * tanh_fast(q1.x + cL[3] + cLk[3]);
            pA += q2.y * tanh_fast(q2.x + cH[0] + cHk[0]);
            pA += q3.y * tanh_fast(q3.x + cH[1] + cHk[1]);
            pB += q2.y * tanh_fast(q2.x + cH[2] + cHk[2]);
            pB += q3.y * tanh_fast(q3.x + cH[3] + cHk[3]);
        }
    }
    if (p < p1) {
        float acc[4][4];
        #pragma unroll
        for (int i = 0; i < 4; i++)
            #pragma unroll
            for (int j = 0; j < 4; j++) acc[i][j] = 0.f;
        uint32_t bpA = b_base + (uint32_t)(p * 16 * LD * 2);
        #pragma unroll
        for (int s = 0; s < 13; s++) {
            int o = (s < 6) ? 0 : 2;
            uint32_t ba_[4];
            ldsm4(ba_, bpA + (uint32_t)(s * 32));
            mma16816(acc[o + 0], afr[s], ba_[0], ba_[1]);
            mma16816(acc[o + 1], afr[s], ba_[2], ba_[3]);
        }
        int n0 = p * 16 + cq;
        float2 q0 = qv[n0],     q1 = qv[n0 + 1];
        float2 q2 = qv[n0 + 8], q3 = qv[n0 + 9];
        pA += q0.y * tanh_fast(q0.x + acc[0][0] + acc[2][0]);
        pA += q1.y * tanh_fast(q1.x + acc[0][1] + acc[2][1]);
        pB += q0.y * tanh_fast(q0.x + acc[0][2] + acc[2][2]);
        pB += q1.y * tanh_fast(q1.x + acc[0][3] + acc[2][3]);
        pA += q2.y * tanh_fast(q2.x + acc[1][0] + acc[3][0]);
        pA += q3.y * tanh_fast(q3.x + acc[1][1] + acc[3][1]);
        pB += q2.y * tanh_fast(q2.x + acc[1][2] + acc[3][2]);
        pB += q3.y * tanh_fast(q3.x + acc[1][3] + acc[3][3]);
    }

    pA += __shfl_xor_sync(~0u, pA, 1); pA += __shfl_xor_sync(~0u, pA, 2);
    pB += __shfl_xor_sync(~0u, pB, 1); pB += __shfl_xor_sync(~0u, pB, 2);
    if ((lid & 3) == 0) {
        int r = lid >> 2;
        sp[nh * 128 + rg * 16 + r]     = pA;
        sp[nh * 128 + rg * 16 + r + 8] = pB;
    }
    __syncthreads();
    if (tid < 128)
        g_sc[b * T_ + t0 + tid] = sp[tid] + sp[128 + tid] + bva[0];
}

// -------- fused softmax + context, float4 high-MLP context loop --------
__global__ void __launch_bounds__(512) softmax_ctx_k(const float* __restrict__ enc) {
    __shared__ float att[T_];            // 8 KB
    __shared__ float part[16][201];      // 12.9 KB
    __shared__ float redm[16], reds[16], sinv;

    int b = blockIdx.x, tid = threadIdx.x, wid = tid >> 5, lid = tid & 31;

    // max
    float v[4], m = -1e30f;
    #pragma unroll
    for (int i = 0; i < 4; i++) { v[i] = g_sc[b * T_ + tid + i * 512]; m = fmaxf(m, v[i]); }
    #pragma unroll
    for (int s = 16; s; s >>= 1) m = fmaxf(m, __shfl_xor_sync(~0u, m, s));
    if (lid == 0) redm[wid] = m;
    __syncthreads();
    if (tid < 32) {
        float mm = (lid < 16) ? redm[lid] : -1e30f;
        #pragma unroll
        for (int s = 8; s; s >>= 1) mm = fmaxf(mm, __shfl_xor_sync(~0u, mm, s));
        if (lid == 0) redm[0] = mm;
    }
    __syncthreads();
    m = redm[0];

    // exp + sum
    float sum = 0.f;
    #pragma unroll
    for (int i = 0; i < 4; i++) { float e = __expf(v[i] - m); att[tid + i * 512] = e; sum += e; }
    #pragma unroll
    for (int s = 16; s; s >>= 1) sum += __shfl_xor_sync(~0u, sum, s);
    if (lid == 0) reds[wid] = sum;
    __syncthreads();
    if (tid < 32) {
        float ss = (lid < 16) ? reds[lid] : 0.f;
        #pragma unroll
        for (int s = 8; s; s >>= 1) ss += __shfl_xor_sync(~0u, ss, s);
        if (lid == 0) sinv = 1.f / ss;
    }
    __syncthreads();

    // context: warp wid owns t in [wid*128, (wid+1)*128); float4 lanes (50 f4/row)
    float4 a0 = make_float4(0.f, 0.f, 0.f, 0.f);
    float4 a1 = make_float4(0.f, 0.f, 0.f, 0.f);
    const float4* eb4 = (const float4*)(enc + ((size_t)b * T_ + wid * 128) * H_);
    #pragma unroll 2
    for (int t = 0; t < 128; t++) {
        float a = att[wid * 128 + t];
        const float4* er = eb4 + t * 50;
        float4 v0 = er[lid];
        a0.x += a * v0.x; a0.y += a * v0.y; a0.z += a * v0.z; a0.w += a * v0.w;
        if (lid < 18) {
            float4 v1 = er[32 + lid];
            a1.x += a * v1.x; a1.y += a * v1.y; a1.z += a * v1.z; a1.w += a * v1.w;
        }
    }
    part[wid][lid * 4 + 0] = a0.x; part[wid][lid * 4 + 1] = a0.y;
    part[wid][lid * 4 + 2] = a0.z; part[wid][lid * 4 + 3] = a0.w;
    if (lid < 18) {      // lanes 0..17 cover h = 128..199 inclusive (all in-row: rows are exactly 50 float4)
        part[wid][128 + lid * 4 + 0] = a1.x;
        part[wid][128 + lid * 4 + 1] = a1.y;
        part[wid][128 + lid * 4 + 2] = a1.z;
        part[wid][128 + lid * 4 + 3] = a1.w;     // FIX: h=199 (lid=17) must be written too
    }
    __syncthreads();
    if (tid < H_) {
        float s2 = 0.f;
        #pragma unroll
        for (int w = 0; w < 16; w++) s2 += part[w][tid];
        g_ctx[b * H_ + tid] = s2 * sinv;
    }
}

// -------- decoder: 512 threads, warp-cooperative coalesced GEMVs + 5 tiny steps --------
__global__ void __launch_bounds__(512) decoder_k(
                          const float* __restrict__ x,  const float* __restrict__ c0,
                          const float* __restrict__ Wih, const float* __restrict__ bih,
                          const float* __restrict__ W1, const float* __restrict__ b1,
                          const float* __restrict__ W2, const float* __restrict__ b2,
                          const float* __restrict__ W3, const float* __restrict__ b3,
                          float* __restrict__ out) {
    int b = blockIdx.x, tid = threadIdx.x, wid = tid >> 5, lid = tid & 31;
    __shared__ float ctx[H_], gb[G4], wcol[G4], c0s[H_], r0s[H_], l1s[100], l2s[50];
    __shared__ float xs;
    if (tid < H_) {
        ctx[tid] = g_ctx[b * H_ + tid];
        c0s[tid] = c0[b * H_ + tid];
    }
    if (tid == 0) xs = x[b];
    for (int g = tid; g < G4; g += 512) wcol[g] = Wih[g * 201];
    __syncthreads();
    for (int g = wid; g < G4; g += 16) {
        const float* w = Wih + g * 201 + 1;
        float acc = 0.f;
        #pragma unroll
        for (int k = lid; k < H_; k += 32) acc += ctx[k] * w[k];
        acc = wred(acc);
        if (lid == 0) gb[g] = acc + bih[g] + g_hpre[b * G4 + g];
    }
    __syncthreads();
    float xv = xs;
    for (int st = 0; st < 5; st++) {
        if (tid < H_) {
            float gi = gb[tid]          + xv * wcol[tid];
            float gf = gb[H_ + tid]     + xv * wcol[H_ + tid];
            float gg = gb[2 * H_ + tid] + xv * wcol[2 * H_ + tid];
            float go = gb[3 * H_ + tid] + xv * wcol[3 * H_ + tid];
            float c  = fast_sig(gf) * c0s[tid] + fast_sig(gi) * ref_tanh(gg);
            float h  = fast_sig(go) * ref_tanh(c);
            r0s[tid] = fmaxf(h, 0.f);
        }
        __syncthreads();
        for (int r = wid; r < 100; r += 16) {
            const float* w = W1 + r * H_;
            float acc = 0.f;
            #pragma unroll
            for (int k = lid; k < H_; k += 32) acc += r0s[k] * w[k];
            acc = wred(acc);
            if (lid == 0) l1s[r] = fmaxf(acc + b1[r], 0.f);
        }
        __syncthreads();
        for (int r = wid; r < 50; r += 16) {
            const float* w = W2 + r * 100;
            float acc = 0.f;
            #pragma unroll
            for (int k = lid; k < 100; k += 32) acc += l1s[k] * w[k];
            acc = wred(acc);
            if (lid == 0) l2s[r] = fmaxf(acc + b2[r], 0.f);
        }
        __syncthreads();
        if (wid == 0) {
            float acc = 0.f;
            for (int k = lid; k < 50; k += 32) acc += l2s[k] * W3[k];
            acc = wred(acc);
            if (lid == 0) { float y = acc + b3[0]; out[b * 5 + st] = y; xs = y; }
        }
        __syncthreads();
        xv = xs;
    }
}

extern "C" void kernel_launch(void* const* d_in, const int* in_sizes, int n_in,
                              void* d_out, int out_size) {
    const float* x   = (const float*)d_in[0];
    const float* h0  = (const float*)d_in[1];
    const float* c0  = (const float*)d_in[2];
    const float* enc = (const float*)d_in[3];
    const float* Wa  = (const float*)d_in[4];
    const float* ba  = (const float*)d_in[5];
    const float* Ua  = (const float*)d_in[6];
    const float* bua = (const float*)d_in[7];
    const float* Va  = (const float*)d_in[8];
    const float* bva = (const float*)d_in[9];
    const float* Wih = (const float*)d_in[10];
    const float* Whh = (const float*)d_in[11];
    const float* bih = (const float*)d_in[12];
    const float* bhh = (const float*)d_in[13];
    const float* W1  = (const float*)d_in[14];
    const float* b1  = (const float*)d_in[15];
    const float* W2  = (const float*)d_in[16];
    const float* b2  = (const float*)d_in[17];
    const float* W3  = (const float*)d_in[18];
    const float* b3  = (const float*)d_in[19];
    float* out = (float*)d_out;

    // Uniform smem carveout across ALL kernels -> no per-node SM reconfiguration
    cudaFuncSetAttribute(prep_k,        cudaFuncAttributePreferredSharedMemoryCarveout, 100);
    cudaFuncSetAttribute(scores_k,      cudaFuncAttributePreferredSharedMemoryCarveout, 100);
    cudaFuncSetAttribute(softmax_ctx_k, cudaFuncAttributePreferredSharedMemoryCarveout, 100);
    cudaFuncSetAttribute(decoder_k,     cudaFuncAttributePreferredSharedMemoryCarveout, 100);
    cudaFuncSetAttribute(scores_k, cudaFuncAttributeMaxDynamicSharedMemorySize, SM_TOT);

    prep_k<<<HP + B_, 512>>>(Ua, h0, Wa, ba, bua, Whh, bhh);   // launch 1
    scores_k<<<B_ * 16, 512, SM_TOT>>>(enc, Va, bva);          // launch 2
    softmax_ctx_k<<<B_, 512>>>(enc);                           // launch 3
    decoder_k<<<B_, 512>>>(x, c0, Wih, bih, W1, b1, W2, b2, W3, b3, out);  // launch 4 <- profiled
}

// round 9
// speedup vs baseline: 2.3807x; 1.0181x over previous
#include <cuda_runtime.h>
#include <cuda_fp16.h>
#include <cstdint>

#define B_  128
#define T_  2048
#define H_  200
#define HP  208          // N padded to 16
#define LD  216          // smem leading dim in halves (432B rows, conflict-free for ldmatrix)
#define G4  800

// ---------------- device scratch ----------------
__device__ __align__(16) half g_Ua[HP * LD];   // Ua fp16, [n][k] row-major, zero-padded
__device__ float g_qadd[B_ * HP];
__device__ float g_hpre[B_ * G4];
__device__ float g_sc[B_ * T_];
__device__ float g_ctx[B_ * H_];

// ---------------- helpers ----------------
__device__ __forceinline__ uint32_t smem_u32(const void* p) {
    uint32_t a;
    asm("{ .reg .u64 t; cvta.to.shared.u64 t, %1; cvt.u32.u64 %0, t; }" : "=r"(a) : "l"(p));
    return a;
}
__device__ __forceinline__ void ldsm4(uint32_t* r, uint32_t addr) {
    asm volatile("ldmatrix.sync.aligned.m8n8.x4.shared.b16 {%0,%1,%2,%3}, [%4];"
                 : "=r"(r[0]), "=r"(r[1]), "=r"(r[2]), "=r"(r[3]) : "r"(addr));
}
__device__ __forceinline__ void mma16816(float* d, const uint32_t* a, uint32_t b0, uint32_t b1) {
    asm volatile("mma.sync.aligned.m16n8k16.row.col.f32.f16.f16.f32 "
                 "{%0,%1,%2,%3}, {%4,%5,%6,%7}, {%8,%9}, {%0,%1,%2,%3};"
                 : "+f"(d[0]), "+f"(d[1]), "+f"(d[2]), "+f"(d[3])
                 : "r"(a[0]), "r"(a[1]), "r"(a[2]), "r"(a[3]), "r"(b0), "r"(b1));
}
__device__ __forceinline__ float tanh_fast(float x) {
    float y;
    asm("tanh.approx.f32 %0, %1;" : "=f"(y) : "f"(x));
    return y;
}
__device__ __forceinline__ float fast_sig(float x) {
    return __fdividef(1.f, 1.f + __expf(-x));
}
__device__ __forceinline__ float ref_tanh(float x) {
    float e = __expf(2.f * x);
    return 1.f - __fdividef(2.f, e + 1.f);
}
__device__ __forceinline__ float wred(float v) {
    v += __shfl_xor_sync(~0u, v, 16); v += __shfl_xor_sync(~0u, v, 8);
    v += __shfl_xor_sync(~0u, v, 4);  v += __shfl_xor_sync(~0u, v, 2);
    v += __shfl_xor_sync(~0u, v, 1);  return v;
}
__device__ __forceinline__ float qred(float v) {   // reduce among 8 lanes of a quarter-warp
    v += __shfl_xor_sync(~0u, v, 1);
    v += __shfl_xor_sync(~0u, v, 2);
    v += __shfl_xor_sync(~0u, v, 4);
    return v;
}

// -------- prep: Ua -> fp16 [n][LD] row-major, zero-padded --------
__global__ void prep_ua(const float* __restrict__ Ua) {
    int n = blockIdx.x, k = threadIdx.x;
    if (k < LD) {
        float v = (n < H_ && k < H_) ? Ua[n * H_ + k] : 0.f;
        g_Ua[n * LD + k] = __float2half(v);
    }
}

// -------- prep: qadd --------
__global__ void prep_q(const float* __restrict__ h0, const float* __restrict__ Wa,
                       const float* __restrict__ ba, const float* __restrict__ bua) {
    int b = blockIdx.x, tid = threadIdx.x, wid = tid >> 5, lid = tid & 31;
    __shared__ float hs[H_];
    if (tid < H_) hs[tid] = h0[b * H_ + tid];
    __syncthreads();
    for (int r = wid; r < HP; r += 8) {
        float acc = 0.f;
        if (r < H_) {
            const float* w = Wa + r * H_;
            #pragma unroll
            for (int k = lid; k < H_; k += 32) acc += hs[k] * w[k];
        }
        acc = wred(acc);
        if (lid == 0) g_qadd[b * HP + r] = (r < H_) ? acc + ba[r] + bua[r] : 0.f;
    }
}

// -------- prep: h_pre --------
__global__ void prep_h(const float* __restrict__ h0, const float* __restrict__ Whh,
                       const float* __restrict__ bhh) {
    int b = blockIdx.x, tid = threadIdx.x, wid = tid >> 5, lid = tid & 31;
    __shared__ float hs[H_];
    if (tid < H_) hs[tid] = h0[b * H_ + tid];
    __syncthreads();
    for (int r = wid; r < G4; r += 8) {
        const float* w = Whh + r * H_;
        float acc = 0.f;
        #pragma unroll
        for (int k = lid; k < H_; k += 32) acc += hs[k] * w[k];
        acc = wred(acc);
        if (lid == 0) g_hpre[b * G4 + r] = acc + bhh[r];
    }
}

// -------- fused scores via raw mma.sync, max chain parallelism --------
#define SM_AS   0
#define SM_BS   (128 * LD * 2)                   // 55296
#define SM_QV   (SM_BS + HP * LD * 2)            // 145152
#define SM_SP   (SM_QV + HP * 8)                 // 146816  partial scores [2][128]
#define SM_TOT  (SM_SP + 256 * 4)                // 147840

__global__ void __launch_bounds__(512) scores_k(const float* __restrict__ enc,
                                                const float* __restrict__ Va,
                                                const float* __restrict__ bva) {
    extern __shared__ char sm[];
    half*   As = (half*)(sm + SM_AS);
    half*   Bs = (half*)(sm + SM_BS);
    float2* qv = (float2*)(sm + SM_QV);
    float*  sp = (float*)(sm + SM_SP);

    int tid = threadIdx.x, wid = tid >> 5, lid = tid & 31;
    int b  = blockIdx.x >> 4;
    int t0 = (blockIdx.x & 15) << 7;

    {
        const uint4* s4 = (const uint4*)g_Ua;
        uint4* d4 = (uint4*)Bs;
        for (int i = tid; i < (HP * LD * 2) / 16; i += 512) d4[i] = s4[i];
    }
    if (tid < HP) qv[tid] = make_float2(g_qadd[b * HP + tid], (tid < H_) ? Va[tid] : 0.f);

    const float* encb = enc + (size_t)(b * T_ + t0) * H_;
    for (int u = tid; u < 128 * 27; u += 512) {
        int row = u / 27, oc = u % 27, k = oc * 8;
        uint4 v;
        half2* hp = (half2*)&v;
        if (k < H_) {
            const float4 f0 = *(const float4*)(encb + row * H_ + k);
            const float4 f1 = *(const float4*)(encb + row * H_ + k + 4);
            hp[0] = __floats2half2_rn(f0.x, f0.y);
            hp[1] = __floats2half2_rn(f0.z, f0.w);
            hp[2] = __floats2half2_rn(f1.x, f1.y);
            hp[3] = __floats2half2_rn(f1.z, f1.w);
        } else {
            v = make_uint4(0, 0, 0, 0);
        }
        *(uint4*)(As + row * LD + k) = v;
    }
    __syncthreads();

    int rg = wid & 7, nh = wid >> 3;
    int lr = lid & 7, quad = lid >> 3;
    uint32_t a_base = smem_u32(As) + (uint32_t)(((rg * 16) + (quad & 1) * 8 + lr) * LD + (quad >> 1) * 8) * 2u;
    uint32_t b_base = smem_u32(Bs) + (uint32_t)((((quad >> 1) * 8) + lr) * LD + (quad & 1) * 8) * 2u;

    uint32_t afr[13][4];
    #pragma unroll
    for (int s = 0; s < 13; s++) ldsm4(afr[s], a_base + (uint32_t)(s * 32));

    float pA = 0.f, pB = 0.f;
    int cq = (lid & 3) * 2;
    int p0 = nh ? 7 : 0, p1 = nh ? 13 : 7;

    int p = p0;
    for (; p + 1 < p1; p += 2) {
        float acc[8][4];
        #pragma unroll
        for (int i = 0; i < 8; i++)
            #pragma unroll
            for (int j = 0; j < 4; j++) acc[i][j] = 0.f;
        uint32_t bpA = b_base + (uint32_t)(p * 16 * LD * 2);
        uint32_t bpB = bpA + (uint32_t)(16 * LD * 2);
        #pragma unroll
        for (int s = 0; s < 13; s++) {
            int o = (s < 6) ? 0 : 4;
            uint32_t ba_[4], bb_[4];
            ldsm4(ba_, bpA + (uint32_t)(s * 32));
            ldsm4(bb_, bpB + (uint32_t)(s * 32));
            mma16816(acc[o + 0], afr[s], ba_[0], ba_[1]);
            mma16816(acc[o + 1], afr[s], ba_[2], ba_[3]);
            mma16816(acc[o + 2], afr[s], bb_[0], bb_[1]);
            mma16816(acc[o + 3], afr[s], bb_[2], bb_[3]);
        }
        #pragma unroll
        for (int t = 0; t < 2; t++) {
            int n0 = (p + t) * 16 + cq;
            float2 q0 = qv[n0],     q1 = qv[n0 + 1];
            float2 q2 = qv[n0 + 8], q3 = qv[n0 + 9];
            float* cL = acc[t * 2];
            float* cLk = acc[t * 2 + 4];
            float* cH = acc[t * 2 + 1];
            float* cHk = acc[t * 2 + 5];
            pA += q0.y * tanh_fast(q0.x + cL[0] + cLk[0]);
            pA += q1.y * tanh_fast(q1.x + cL[1] + cLk[1]);
            pB += q0.y * tanh_fast(q0.x + cL[2] + cLk[2]);
            pB += q1.y * tanh_fast(q1.x + cL[3] + cLk[3]);
            pA += q2.y * tanh_fast(q2.x + cH[0] + cHk[0]);
            pA += q3.y * tanh_fast(q3.x + cH[1] + cHk[1]);
            pB += q2.y * tanh_fast(q2.x + cH[2] + cHk[2]);
            pB += q3.y * tanh_fast(q3.x + cH[3] + cHk[3]);
        }
    }
    if (p < p1) {
        float acc[4][4];
        #pragma unroll
        for (int i = 0; i < 4; i++)
            #pragma unroll
            for (int j = 0; j < 4; j++) acc[i][j] = 0.f;
        uint32_t bpA = b_base + (uint32_t)(p * 16 * LD * 2);
        #pragma unroll
        for (int s = 0; s < 13; s++) {
            int o = (s < 6) ? 0 : 2;
            uint32_t ba_[4];
            ldsm4(ba_, bpA + (uint32_t)(s * 32));
            mma16816(acc[o + 0], afr[s], ba_[0], ba_[1]);
            mma16816(acc[o + 1], afr[s], ba_[2], ba_[3]);
        }
        int n0 = p * 16 + cq;
        float2 q0 = qv[n0],     q1 = qv[n0 + 1];
        float2 q2 = qv[n0 + 8], q3 = qv[n0 + 9];
        pA += q0.y * tanh_fast(q0.x + acc[0][0] + acc[2][0]);
        pA += q1.y * tanh_fast(q1.x + acc[0][1] + acc[2][1]);
        pB += q0.y * tanh_fast(q0.x + acc[0][2] + acc[2][2]);
        pB += q1.y * tanh_fast(q1.x + acc[0][3] + acc[2][3]);
        pA += q2.y * tanh_fast(q2.x + acc[1][0] + acc[3][0]);
        pA += q3.y * tanh_fast(q3.x + acc[1][1] + acc[3][1]);
        pB += q2.y * tanh_fast(q2.x + acc[1][2] + acc[3][2]);
        pB += q3.y * tanh_fast(q3.x + acc[1][3] + acc[3][3]);
    }

    pA += __shfl_xor_sync(~0u, pA, 1); pA += __shfl_xor_sync(~0u, pA, 2);
    pB += __shfl_xor_sync(~0u, pB, 1); pB += __shfl_xor_sync(~0u, pB, 2);
    if ((lid & 3) == 0) {
        int r = lid >> 2;
        sp[nh * 128 + rg * 16 + r]     = pA;
        sp[nh * 128 + rg * 16 + r + 8] = pB;
    }
    __syncthreads();
    if (tid < 128)
        g_sc[b * T_ + t0 + tid] = sp[tid] + sp[128 + tid] + bva[0];
}

// -------- fused softmax + context, float4 high-MLP context loop --------
__global__ void __launch_bounds__(512) softmax_ctx_k(const float* __restrict__ enc) {
    __shared__ float att[T_];            // 8 KB
    __shared__ float part[16][201];      // 12.9 KB
    __shared__ float redm[16], reds[16], sinv;

    int b = blockIdx.x, tid = threadIdx.x, wid = tid >> 5, lid = tid & 31;

    float v[4], m = -1e30f;
    #pragma unroll
    for (int i = 0; i < 4; i++) { v[i] = g_sc[b * T_ + tid + i * 512]; m = fmaxf(m, v[i]); }
    #pragma unroll
    for (int s = 16; s; s >>= 1) m = fmaxf(m, __shfl_xor_sync(~0u, m, s));
    if (lid == 0) redm[wid] = m;
    __syncthreads();
    if (tid < 32) {
        float mm = (lid < 16) ? redm[lid] : -1e30f;
        #pragma unroll
        for (int s = 8; s; s >>= 1) mm = fmaxf(mm, __shfl_xor_sync(~0u, mm, s));
        if (lid == 0) redm[0] = mm;
    }
    __syncthreads();
    m = redm[0];

    float sum = 0.f;
    #pragma unroll
    for (int i = 0; i < 4; i++) { float e = __expf(v[i] - m); att[tid + i * 512] = e; sum += e; }
    #pragma unroll
    for (int s = 16; s; s >>= 1) sum += __shfl_xor_sync(~0u, sum, s);
    if (lid == 0) reds[wid] = sum;
    __syncthreads();
    if (tid < 32) {
        float ss = (lid < 16) ? reds[lid] : 0.f;
        #pragma unroll
        for (int s = 8; s; s >>= 1) ss += __shfl_xor_sync(~0u, ss, s);
        if (lid == 0) sinv = 1.f / ss;
    }
    __syncthreads();

    float4 a0 = make_float4(0.f, 0.f, 0.f, 0.f);
    float4 a1 = make_float4(0.f, 0.f, 0.f, 0.f);
    const float4* eb4 = (const float4*)(enc + ((size_t)b * T_ + wid * 128) * H_);
    #pragma unroll 2
    for (int t = 0; t < 128; t++) {
        float a = att[wid * 128 + t];
        const float4* er = eb4 + t * 50;
        float4 v0 = er[lid];
        a0.x += a * v0.x; a0.y += a * v0.y; a0.z += a * v0.z; a0.w += a * v0.w;
        if (lid < 18) {
            float4 v1 = er[32 + lid];
            a1.x += a * v1.x; a1.y += a * v1.y; a1.z += a * v1.z; a1.w += a * v1.w;
        }
    }
    part[wid][lid * 4 + 0] = a0.x; part[wid][lid * 4 + 1] = a0.y;
    part[wid][lid * 4 + 2] = a0.z; part[wid][lid * 4 + 3] = a0.w;
    if (lid < 18) {
        part[wid][128 + lid * 4 + 0] = a1.x;
        part[wid][128 + lid * 4 + 1] = a1.y;
        part[wid][128 + lid * 4 + 2] = a1.z;
        part[wid][128 + lid * 4 + 3] = a1.w;
    }
    __syncthreads();
    if (tid < H_) {
        float s2 = 0.f;
        #pragma unroll
        for (int w = 0; w < 16; w++) s2 += part[w][tid];
        g_ctx[b * H_ + tid] = s2 * sinv;
    }
}

// -------- decoder: smem-resident weights + quarter-warp GEMVs (shuffle-safe) --------
// dynamic smem: W1 [100][200] | W2 [50][104] (padded, conflict-free) | W3 [50]
#define DW1   0
#define DW2   (100 * 200)            // 20000 floats
#define DW3   (DW2 + 50 * 104)       // 25200
#define DSM_FLOATS (DW3 + 64)        // 25264
#define DSM_TOT (DSM_FLOATS * 4)     // 101056 B

__global__ void __launch_bounds__(512) decoder_k(
                          const float* __restrict__ x,  const float* __restrict__ c0,
                          const float* __restrict__ Wih, const float* __restrict__ bih,
                          const float* __restrict__ W1, const float* __restrict__ b1,
                          const float* __restrict__ W2, const float* __restrict__ b2,
                          const float* __restrict__ W3, const float* __restrict__ b3,
                          float* __restrict__ out) {
    extern __shared__ float dsm[];
    __shared__ float ctx[H_], gb[G4], wcol[G4], c0s[H_], r0s[H_];
    __shared__ float l1s[100], l2s[52], b1s[100], b2s[52];
    __shared__ float xs, b3s;

    int b = blockIdx.x, tid = threadIdx.x, wid = tid >> 5, lid = tid & 31;
    int q = lid >> 3, kl = lid & 7;              // quarter-warp id / lane-in-quarter

    // stage weights into smem (coalesced)
    {
        const float4* s4 = (const float4*)W1;    // 20000 floats = 5000 float4
        float4* d4 = (float4*)(dsm + DW1);
        for (int i = tid; i < 5000; i += 512) d4[i] = s4[i];
    }
    for (int i = tid; i < 5000; i += 512) {      // W2 with pad 100->104
        int r = i / 100, c = i % 100;
        dsm[DW2 + r * 104 + c] = W2[i];
    }
    if (tid < 50)  { dsm[DW3 + tid] = W3[tid]; b2s[tid] = b2[tid]; }
    if (tid < 100) b1s[tid] = b1[tid];
    if (tid < H_) {
        ctx[tid] = g_ctx[b * H_ + tid];
        c0s[tid] = c0[b * H_ + tid];
    }
    if (tid == 0) { xs = x[b]; b3s = b3[0]; }
    for (int g = tid; g < G4; g += 512) wcol[g] = Wih[g * 201];
    __syncthreads();

    // gates base: warp-uniform loop; quarter q handles row base+q (always < 800)
    for (int base = wid * 4; base < G4; base += 64) {
        int g = base + q;
        const float* w = Wih + g * 201 + 1;
        float acc = 0.f;
        #pragma unroll
        for (int k = kl; k < H_; k += 8) acc += ctx[k] * w[k];
        acc = qred(acc);
        if (kl == 0) gb[g] = acc + bih[g] + g_hpre[b * G4 + g];
    }
    __syncthreads();

    float xv = xs;
    for (int st = 0; st < 5; st++) {
        if (tid < H_) {
            float gi = gb[tid]          + xv * wcol[tid];
            float gf = gb[H_ + tid]     + xv * wcol[H_ + tid];
            float gg = gb[2 * H_ + tid] + xv * wcol[2 * H_ + tid];
            float go = gb[3 * H_ + tid] + xv * wcol[3 * H_ + tid];
            float c  = fast_sig(gf) * c0s[tid] + fast_sig(gi) * ref_tanh(gg);
            float h  = fast_sig(go) * ref_tanh(c);
            r0s[tid] = fmaxf(h, 0.f);
        }
        __syncthreads();
        // W1: 100x200 from smem; warp-uniform loop, row base+q < 100 always
        for (int base = wid * 4; base < 100; base += 64) {
            int r = base + q;
            const float* w = dsm + DW1 + r * 200;
            float acc = 0.f;
            #pragma unroll
            for (int k = kl; k < H_; k += 8) acc += r0s[k] * w[k];
            acc = qred(acc);
            if (kl == 0) l1s[r] = fmaxf(acc + b1s[r], 0.f);
        }
        __syncthreads();
        // W2: 50x100 from smem; warp-uniform guard (warps 0..12), lane-guarded accumulate,
        // ALL lanes of participating warps execute qred -> no shuffle deadlock
        {
            int base = wid * 4;
            if (base < 52) {
                int r = base + q;
                float acc = 0.f;
                if (r < 50) {
                    const float* w = dsm + DW2 + r * 104;
                    #pragma unroll
                    for (int k = kl; k < 100; k += 8) acc += l1s[k] * w[k];
                }
                acc = qred(acc);
                if (kl == 0 && r < 50) l2s[r] = fmaxf(acc + b2s[r], 0.f);
            }
        }
        __syncthreads();
        // W3: 1x50, warp 0
        if (wid == 0) {
            float acc = 0.f;
            #pragma unroll
            for (int k = lid; k < 50; k += 32) acc += l2s[k] * dsm[DW3 + k];
            acc = wred(acc);
            if (lid == 0) { float y = acc + b3s; out[b * 5 + st] = y; xs = y; }
        }
        __syncthreads();
        xv = xs;
    }
}

extern "C" void kernel_launch(void* const* d_in, const int* in_sizes, int n_in,
                              void* d_out, int out_size) {
    const float* x   = (const float*)d_in[0];
    const float* h0  = (const float*)d_in[1];
    const float* c0  = (const float*)d_in[2];
    const float* enc = (const float*)d_in[3];
    const float* Wa  = (const float*)d_in[4];
    const float* ba  = (const float*)d_in[5];
    const float* Ua  = (const float*)d_in[6];
    const float* bua = (const float*)d_in[7];
    const float* Va  = (const float*)d_in[8];
    const float* bva = (const float*)d_in[9];
    const float* Wih = (const float*)d_in[10];
    const float* Whh = (const float*)d_in[11];
    const float* bih = (const float*)d_in[12];
    const float* bhh = (const float*)d_in[13];
    const float* W1  = (const float*)d_in[14];
    const float* b1  = (const float*)d_in[15];
    const float* W2  = (const float*)d_in[16];
    const float* b2  = (const float*)d_in[17];
    const float* W3  = (const float*)d_in[18];
    const float* b3  = (const float*)d_in[19];
    float* out = (float*)d_out;

    // Uniform smem carveout across ALL kernels -> no per-node SM reconfiguration
    cudaFuncSetAttribute(prep_ua,       cudaFuncAttributePreferredSharedMemoryCarveout, 100);
    cudaFuncSetAttribute(prep_q,        cudaFuncAttributePreferredSharedMemoryCarveout, 100);
    cudaFuncSetAttribute(prep_h,        cudaFuncAttributePreferredSharedMemoryCarveout, 100);
    cudaFuncSetAttribute(scores_k,      cudaFuncAttributePreferredSharedMemoryCarveout, 100);
    cudaFuncSetAttribute(softmax_ctx_k, cudaFuncAttributePreferredSharedMemoryCarveout, 100);
    cudaFuncSetAttribute(decoder_k,     cudaFuncAttributePreferredSharedMemoryCarveout, 100);
    cudaFuncSetAttribute(scores_k,  cudaFuncAttributeMaxDynamicSharedMemorySize, SM_TOT);
    cudaFuncSetAttribute(decoder_k, cudaFuncAttributeMaxDynamicSharedMemorySize, DSM_TOT);

    prep_ua<<<HP, 256>>>(Ua);                                  // launch 1
    prep_q<<<B_, 256>>>(h0, Wa, ba, bua);                      // launch 2
    prep_h<<<B_, 256>>>(h0, Whh, bhh);                         // launch 3
    scores_k<<<B_ * 16, 512, SM_TOT>>>(enc, Va, bva);          // launch 4 <- profiled
    softmax_ctx_k<<<B_, 512>>>(enc);                           // launch 5
    decoder_k<<<B_, 512, DSM_TOT>>>(x, c0, Wih, bih, W1, b1, W2, b2, W3, b3, out);  // launch 6
}

// round 12
// speedup vs baseline: 2.5132x; 1.0556x over previous
#include <cuda_runtime.h>
#include <cuda_fp16.h>
#include <cstdint>

#define B_  128
#define T_  2048
#define H_  200
#define HP  208          // N padded to 16
#define LD  216          // smem leading dim in halves (432B rows, conflict-free for ldmatrix)
#define G4  800

// ---------------- device scratch ----------------
__device__ __align__(16) half g_Ua[HP * LD];   // Ua fp16, [n][k] row-major, zero-padded
__device__ float g_qadd[B_ * HP];
__device__ float g_hpre[B_ * G4];
__device__ float g_sc0[B_ * T_];               // scores partial, n-half 0 (+bva)
__device__ float g_sc1[B_ * T_];               // scores partial, n-half 1
__device__ float g_ctx[B_ * H_];

// ---------------- helpers ----------------
__device__ __forceinline__ uint32_t smem_u32(const void* p) {
    uint32_t a;
    asm("{ .reg .u64 t; cvta.to.shared.u64 t, %1; cvt.u32.u64 %0, t; }" : "=r"(a) : "l"(p));
    return a;
}
__device__ __forceinline__ void ldsm4(uint32_t* r, uint32_t addr) {
    asm volatile("ldmatrix.sync.aligned.m8n8.x4.shared.b16 {%0,%1,%2,%3}, [%4];"
                 : "=r"(r[0]), "=r"(r[1]), "=r"(r[2]), "=r"(r[3]) : "r"(addr));
}
__device__ __forceinline__ void mma16816(float* d, const uint32_t* a, uint32_t b0, uint32_t b1) {
    asm volatile("mma.sync.aligned.m16n8k16.row.col.f32.f16.f16.f32 "
                 "{%0,%1,%2,%3}, {%4,%5,%6,%7}, {%8,%9}, {%0,%1,%2,%3};"
                 : "+f"(d[0]), "+f"(d[1]), "+f"(d[2]), "+f"(d[3])
                 : "r"(a[0]), "r"(a[1]), "r"(a[2]), "r"(a[3]), "r"(b0), "r"(b1));
}
__device__ __forceinline__ float tanh_fast(float x) {
    float y;
    asm("tanh.approx.f32 %0, %1;" : "=f"(y) : "f"(x));
    return y;
}
__device__ __forceinline__ float fast_sig(float x) {
    return __fdividef(1.f, 1.f + __expf(-x));
}
__device__ __forceinline__ float ref_tanh(float x) {
    float e = __expf(2.f * x);
    return 1.f - __fdividef(2.f, e + 1.f);
}
__device__ __forceinline__ float wred(float v) {
    v += __shfl_xor_sync(~0u, v, 16); v += __shfl_xor_sync(~0u, v, 8);
    v += __shfl_xor_sync(~0u, v, 4);  v += __shfl_xor_sync(~0u, v, 2);
    v += __shfl_xor_sync(~0u, v, 1);  return v;
}
__device__ __forceinline__ float qred(float v) {
    v += __shfl_xor_sync(~0u, v, 1);
    v += __shfl_xor_sync(~0u, v, 2);
    v += __shfl_xor_sync(~0u, v, 4);
    return v;
}

// -------- prep: Ua -> fp16 [n][LD] row-major, zero-padded --------
__global__ void prep_ua(const float* __restrict__ Ua) {
    int n = blockIdx.x, k = threadIdx.x;
    if (k < LD) {
        float v = (n < H_ && k < H_) ? Ua[n * H_ + k] : 0.f;
        g_Ua[n * LD + k] = __float2half(v);
    }
}

// -------- prep: qadd + h_pre --------
__global__ void prep_qh(const float* __restrict__ h0, const float* __restrict__ Wa,
                        const float* __restrict__ ba, const float* __restrict__ bua,
                        const float* __restrict__ Whh, const float* __restrict__ bhh) {
    int b = blockIdx.x, tid = threadIdx.x, wid = tid >> 5, lid = tid & 31;
    __shared__ float hs[H_];
    if (tid < H_) hs[tid] = h0[b * H_ + tid];
    __syncthreads();
    for (int r = wid; r < HP; r += 8) {
        float acc = 0.f;
        if (r < H_) {
            const float* w = Wa + r * H_;
            #pragma unroll
            for (int k = lid; k < H_; k += 32) acc += hs[k] * w[k];
        }
        acc = wred(acc);
        if (lid == 0) g_qadd[b * HP + r] = (r < H_) ? acc + ba[r] + bua[r] : 0.f;
    }
    for (int r = wid; r < G4; r += 8) {
        const float* w = Whh + r * H_;
        float acc = 0.f;
        #pragma unroll
        for (int k = lid; k < H_; k += 32) acc += hs[k] * w[k];
        acc = wred(acc);
        if (lid == 0) g_hpre[b * G4 + r] = acc + bhh[r];
    }
}

// -------- scores: two-phase smem + N-split -> 3 CTAs/SM --------
// grid 4096: bidx = ((b*16 + tt)*2 + nh); 256 threads = 8 warps, warp = 16-row group.
// Phase 1: stage 128-row enc tile (55296B), cache A fragments in regs.
// Phase 2: overwrite same smem with this CTA's Ua n-slice (<=48384B), run MMA.
#define SMREG   55296                     // max(As, Bs_half)
#define SM_QV2  SMREG                     // float2 qv[HP]
#define SM2_TOT (SMREG + HP * 8 + 64)     // 57024 B

__global__ void __launch_bounds__(256, 3) scores_k(const float* __restrict__ enc,
                                                   const float* __restrict__ Va,
                                                   const float* __restrict__ bva) {
    extern __shared__ char sm[];
    half*   Reg = (half*)sm;
    float2* qv  = (float2*)(sm + SM_QV2);

    int tid = threadIdx.x, wid = tid >> 5, lid = tid & 31;
    int bidx = blockIdx.x;
    int nh = bidx & 1;
    int tt = (bidx >> 1) & 15;
    int b  = bidx >> 5;
    int t0 = tt << 7;
    int n0 = nh ? 112 : 0;
    int np = nh ? 6 : 7;                 // 16-wide n-tiles in this half

    // ---- phase 1: stage enc tile [128][LD] fp16 ----
    const float* encb = enc + (size_t)(b * T_ + t0) * H_;
    for (int u = tid; u < 128 * 27; u += 256) {
        int row = u / 27, oc = u % 27, k = oc * 8;
        uint4 v;
        half2* hp = (half2*)&v;
        if (k < H_) {
            const float4 f0 = *(const float4*)(encb + row * H_ + k);
            const float4 f1 = *(const float4*)(encb + row * H_ + k + 4);
            hp[0] = __floats2half2_rn(f0.x, f0.y);
            hp[1] = __floats2half2_rn(f0.z, f0.w);
            hp[2] = __floats2half2_rn(f1.x, f1.y);
            hp[3] = __floats2half2_rn(f1.z, f1.w);
        } else {
            v = make_uint4(0, 0, 0, 0);
        }
        *(uint4*)(Reg + row * LD + k) = v;
    }
    if (tid < HP) qv[tid] = make_float2(g_qadd[b * HP + tid], (tid < H_) ? Va[tid] : 0.f);
    __syncthreads();

    // cache A fragments for this warp's 16 rows
    int lr = lid & 7, quad = lid >> 3;
    uint32_t a_base = smem_u32(Reg) + (uint32_t)(((wid * 16) + (quad & 1) * 8 + lr) * LD + (quad >> 1) * 8) * 2u;
    uint32_t afr[13][4];
    #pragma unroll
    for (int s = 0; s < 13; s++) ldsm4(afr[s], a_base + (uint32_t)(s * 32));
    __syncthreads();

    // ---- phase 2: overwrite with Ua slice [np*16][LD] ----
    {
        const uint4* s4 = (const uint4*)(g_Ua + n0 * LD);
        uint4* d4 = (uint4*)Reg;
        int cnt = np * 16 * 27;
        for (int i = tid; i < cnt; i += 256) d4[i] = s4[i];
    }
    __syncthreads();

    uint32_t b_base = smem_u32(Reg) + (uint32_t)((((quad >> 1) * 8) + lr) * LD + (quad & 1) * 8) * 2u;
    float pA = 0.f, pB = 0.f;
    int cq = (lid & 3) * 2;

    for (int pl = 0; pl < np; pl++) {
        float a0[4] = {0.f, 0.f, 0.f, 0.f};
        float a1[4] = {0.f, 0.f, 0.f, 0.f};
        float a2[4] = {0.f, 0.f, 0.f, 0.f};
        float a3[4] = {0.f, 0.f, 0.f, 0.f};
        uint32_t bp = b_base + (uint32_t)(pl * 16 * LD * 2);
        #pragma unroll
        for (int s = 0; s < 13; s++) {
            uint32_t bb[4];
            ldsm4(bb, bp + (uint32_t)(s * 32));
            if (s < 7) {
                mma16816(a0, afr[s], bb[0], bb[1]);
                mma16816(a1, afr[s], bb[2], bb[3]);
            } else {
                mma16816(a2, afr[s], bb[0], bb[1]);
                mma16816(a3, afr[s], bb[2], bb[3]);
            }
        }
        int n = n0 + pl * 16 + cq;
        float2 q0 = qv[n],     q1 = qv[n + 1];
        float2 q2 = qv[n + 8], q3 = qv[n + 9];
        pA += q0.y * tanh_fast(q0.x + a0[0] + a2[0]);
        pA += q1.y * tanh_fast(q1.x + a0[1] + a2[1]);
        pB += q0.y * tanh_fast(q0.x + a0[2] + a2[2]);
        pB += q1.y * tanh_fast(q1.x + a0[3] + a2[3]);
        pA += q2.y * tanh_fast(q2.x + a1[0] + a3[0]);
        pA += q3.y * tanh_fast(q3.x + a1[1] + a3[1]);
        pB += q2.y * tanh_fast(q2.x + a1[2] + a3[2]);
        pB += q3.y * tanh_fast(q3.x + a1[3] + a3[3]);
    }

    pA += __shfl_xor_sync(~0u, pA, 1); pA += __shfl_xor_sync(~0u, pA, 2);
    pB += __shfl_xor_sync(~0u, pB, 1); pB += __shfl_xor_sync(~0u, pB, 2);
    if ((lid & 3) == 0) {
        int r = lid >> 2;
        float bv = nh ? 0.f : bva[0];
        float* dst = nh ? g_sc1 : g_sc0;
        dst[b * T_ + t0 + wid * 16 + r]     = pA + bv;
        dst[b * T_ + t0 + wid * 16 + r + 8] = pB + bv;
    }
}

// -------- fused softmax + context (reads both score partials) --------
__global__ void __launch_bounds__(512) softmax_ctx_k(const float* __restrict__ enc) {
    __shared__ float att[T_];
    __shared__ float part[16][201];
    __shared__ float redm[16], reds[16], sinv;

    int b = blockIdx.x, tid = threadIdx.x, wid = tid >> 5, lid = tid & 31;

    float v[4], m = -1e30f;
    #pragma unroll
    for (int i = 0; i < 4; i++) {
        int idx = b * T_ + tid + i * 512;
        v[i] = g_sc0[idx] + g_sc1[idx];
        m = fmaxf(m, v[i]);
    }
    #pragma unroll
    for (int s = 16; s; s >>= 1) m = fmaxf(m, __shfl_xor_sync(~0u, m, s));
    if (lid == 0) redm[wid] = m;
    __syncthreads();
    if (tid < 32) {
        float mm = (lid < 16) ? redm[lid] : -1e30f;
        #pragma unroll
        for (int s = 8; s; s >>= 1) mm = fmaxf(mm, __shfl_xor_sync(~0u, mm, s));
        if (lid == 0) redm[0] = mm;
    }
    __syncthreads();
    m = redm[0];

    float sum = 0.f;
    #pragma unroll
    for (int i = 0; i < 4; i++) { float e = __expf(v[i] - m); att[tid + i * 512] = e; sum += e; }
    #pragma unroll
    for (int s = 16; s; s >>= 1) sum += __shfl_xor_sync(~0u, sum, s);
    if (lid == 0) reds[wid] = sum;
    __syncthreads();
    if (tid < 32) {
        float ss = (lid < 16) ? reds[lid] : 0.f;
        #pragma unroll
        for (int s = 8; s; s >>= 1) ss += __shfl_xor_sync(~0u, ss, s);
        if (lid == 0) sinv = 1.f / ss;
    }
    __syncthreads();

    float4 a0 = make_float4(0.f, 0.f, 0.f, 0.f);
    float4 a1 = make_float4(0.f, 0.f, 0.f, 0.f);
    const float4* eb4 = (const float4*)(enc + ((size_t)b * T_ + wid * 128) * H_);
    #pragma unroll 2
    for (int t = 0; t < 128; t++) {
        float a = att[wid * 128 + t];
        const float4* er = eb4 + t * 50;
        float4 v0 = er[lid];
        a0.x += a * v0.x; a0.y += a * v0.y; a0.z += a * v0.z; a0.w += a * v0.w;
        if (lid < 18) {
            float4 v1 = er[32 + lid];
            a1.x += a * v1.x; a1.y += a * v1.y; a1.z += a * v1.z; a1.w += a * v1.w;
        }
    }
    part[wid][lid * 4 + 0] = a0.x; part[wid][lid * 4 + 1] = a0.y;
    part[wid][lid * 4 + 2] = a0.z; part[wid][lid * 4 + 3] = a0.w;
    if (lid < 18) {
        part[wid][128 + lid * 4 + 0] = a1.x;
        part[wid][128 + lid * 4 + 1] = a1.y;
        part[wid][128 + lid * 4 + 2] = a1.z;
        part[wid][128 + lid * 4 + 3] = a1.w;
    }
    __syncthreads();
    if (tid < H_) {
        float s2 = 0.f;
        #pragma unroll
        for (int w = 0; w < 16; w++) s2 += part[w][tid];
        g_ctx[b * H_ + tid] = s2 * sinv;
    }
}

// -------- decoder: smem-resident weights + quarter-warp GEMVs (shuffle-safe) --------
#define DW1   0
#define DW2   (100 * 200)
#define DW3   (DW2 + 50 * 104)
#define DSM_FLOATS (DW3 + 64)
#define DSM_TOT (DSM_FLOATS * 4)

__global__ void __launch_bounds__(512) decoder_k(
                          const float* __restrict__ x,  const float* __restrict__ c0,
                          const float* __restrict__ Wih, const float* __restrict__ bih,
                          const float* __restrict__ W1, const float* __restrict__ b1,
                          const float* __restrict__ W2, const float* __restrict__ b2,
                          const float* __restrict__ W3, const float* __restrict__ b3,
                          float* __restrict__ out) {
    extern __shared__ float dsm[];
    __shared__ float ctx[H_], gb[G4], wcol[G4], c0s[H_], r0s[H_];
    __shared__ float l1s[100], l2s[52], b1s[100], b2s[52];
    __shared__ float xs, b3s;

    int b = blockIdx.x, tid = threadIdx.x, wid = tid >> 5, lid = tid & 31;
    int q = lid >> 3, kl = lid & 7;

    {
        const float4* s4 = (const float4*)W1;
        float4* d4 = (float4*)(dsm + DW1);
        for (int i = tid; i < 5000; i += 512) d4[i] = s4[i];
    }
    for (int i = tid; i < 5000; i += 512) {
        int r = i / 100, c = i % 100;
        dsm[DW2 + r * 104 + c] = W2[i];
    }
    if (tid < 50)  { dsm[DW3 + tid] = W3[tid]; b2s[tid] = b2[tid]; }
    if (tid < 100) b1s[tid] = b1[tid];
    if (tid < H_) {
        ctx[tid] = g_ctx[b * H_ + tid];
        c0s[tid] = c0[b * H_ + tid];
    }
    if (tid == 0) { xs = x[b]; b3s = b3[0]; }
    for (int g = tid; g < G4; g += 512) wcol[g] = Wih[g * 201];
    __syncthreads();

    for (int base = wid * 4; base < G4; base += 64) {
        int g = base + q;
        const float* w = Wih + g * 201 + 1;
        float acc = 0.f;
        #pragma unroll
        for (int k = kl; k < H_; k += 8) acc += ctx[k] * w[k];
        acc = qred(acc);
        if (kl == 0) gb[g] = acc + bih[g] + g_hpre[b * G4 + g];
    }
    __syncthreads();

    float xv = xs;
    for (int st = 0; st < 5; st++) {
        if (tid < H_) {
            float gi = gb[tid]          + xv * wcol[tid];
            float gf = gb[H_ + tid]     + xv * wcol[H_ + tid];
            float gg = gb[2 * H_ + tid] + xv * wcol[2 * H_ + tid];
            float go = gb[3 * H_ + tid] + xv * wcol[3 * H_ + tid];
            float c  = fast_sig(gf) * c0s[tid] + fast_sig(gi) * ref_tanh(gg);
            float h  = fast_sig(go) * ref_tanh(c);
            r0s[tid] = fmaxf(h, 0.f);
        }
        __syncthreads();
        for (int base = wid * 4; base < 100; base += 64) {
            int r = base + q;
            const float* w = dsm + DW1 + r * 200;
            float acc = 0.f;
            #pragma unroll
            for (int k = kl; k < H_; k += 8) acc += r0s[k] * w[k];
            acc = qred(acc);
            if (kl == 0) l1s[r] = fmaxf(acc + b1s[r], 0.f);
        }
        __syncthreads();
        {
            int base = wid * 4;
            if (base < 52) {
                int r = base + q;
                float acc = 0.f;
                if (r < 50) {
                    const float* w = dsm + DW2 + r * 104;
                    #pragma unroll
                    for (int k = kl; k < 100; k += 8) acc += l1s[k] * w[k];
                }
                acc = qred(acc);
                if (kl == 0 && r < 50) l2s[r] = fmaxf(acc + b2s[r], 0.f);
            }
        }
        __syncthreads();
        if (wid == 0) {
            float acc = 0.f;
            #pragma unroll
            for (int k = lid; k < 50; k += 32) acc += l2s[k] * dsm[DW3 + k];
            acc = wred(acc);
            if (lid == 0) { float y = acc + b3s; out[b * 5 + st] = y; xs = y; }
        }
        __syncthreads();
        xv = xs;
    }
}

extern "C" void kernel_launch(void* const* d_in, const int* in_sizes, int n_in,
                              void* d_out, int out_size) {
    const float* x   = (const float*)d_in[0];
    const float* h0  = (const float*)d_in[1];
    const float* c0  = (const float*)d_in[2];
    const float* enc = (const float*)d_in[3];
    const float* Wa  = (const float*)d_in[4];
    const float* ba  = (const float*)d_in[5];
    const float* Ua  = (const float*)d_in[6];
    const float* bua = (const float*)d_in[7];
    const float* Va  = (const float*)d_in[8];
    const float* bva = (const float*)d_in[9];
    const float* Wih = (const float*)d_in[10];
    const float* Whh = (const float*)d_in[11];
    const float* bih = (const float*)d_in[12];
    const float* bhh = (const float*)d_in[13];
    const float* W1  = (const float*)d_in[14];
    const float* b1  = (const float*)d_in[15];
    const float* W2  = (const float*)d_in[16];
    const float* b2  = (const float*)d_in[17];
    const float* W3  = (const float*)d_in[18];
    const float* b3  = (const float*)d_in[19];
    float* out = (float*)d_out;

    // Uniform smem carveout across ALL kernels -> no per-node SM reconfiguration
    cudaFuncSetAttribute(prep_ua,       cudaFuncAttributePreferredSharedMemoryCarveout, 100);
    cudaFuncSetAttribute(prep_qh,       cudaFuncAttributePreferredSharedMemoryCarveout, 100);
    cudaFuncSetAttribute(scores_k,      cudaFuncAttributePreferredSharedMemoryCarveout, 100);
    cudaFuncSetAttribute(softmax_ctx_k, cudaFuncAttributePreferredSharedMemoryCarveout, 100);
    cudaFuncSetAttribute(decoder_k,     cudaFuncAttributePreferredSharedMemoryCarveout, 100);
    cudaFuncSetAttribute(scores_k,  cudaFuncAttributeMaxDynamicSharedMemorySize, SM2_TOT);
    cudaFuncSetAttribute(decoder_k, cudaFuncAttributeMaxDynamicSharedMemorySize, DSM_TOT);

    prep_ua<<<HP, 256>>>(Ua);                                  // launch 1
    prep_qh<<<B_, 256>>>(h0, Wa, ba, bua, Whh, bhh);           // launch 2
    scores_k<<<B_ * 32, 256, SM2_TOT>>>(enc, Va, bva);         // launch 3
    softmax_ctx_k<<<B_, 512>>>(enc);                           // launch 4 <- profiled
    decoder_k<<<B_, 512, DSM_TOT>>>(x, c0, Wih, bih, W1, b1, W2, b2, W3, b3, out);  // launch 5
}

// round 13
// speedup vs baseline: 2.5950x; 1.0325x over previous
#include <cuda_runtime.h>
#include <cuda_fp16.h>
#include <cstdint>

#define B_  128
#define T_  2048
#define H_  200
#define HP  208          // N padded to 16
#define LD  216          // smem leading dim in halves (432B rows, conflict-free for ldmatrix)
#define G4  800

// ---------------- device scratch ----------------
__device__ __align__(16) half g_Ua[HP * LD];   // Ua fp16, [n][k] row-major, zero-padded
__device__ float g_qadd[B_ * HP];
__device__ float g_hpre[B_ * G4];
__device__ float g_sc0[B_ * T_];               // scores partial n-half 0 (+bva) -> att (normalized)
__device__ float g_sc1[B_ * T_];               // scores partial n-half 1
__device__ float g_ctxp[16 * B_ * H_];         // context partials (att already normalized)

// ---------------- helpers ----------------
__device__ __forceinline__ uint32_t smem_u32(const void* p) {
    uint32_t a;
    asm("{ .reg .u64 t; cvta.to.shared.u64 t, %1; cvt.u32.u64 %0, t; }" : "=r"(a) : "l"(p));
    return a;
}
__device__ __forceinline__ void ldsm4(uint32_t* r, uint32_t addr) {
    asm volatile("ldmatrix.sync.aligned.m8n8.x4.shared.b16 {%0,%1,%2,%3}, [%4];"
                 : "=r"(r[0]), "=r"(r[1]), "=r"(r[2]), "=r"(r[3]) : "r"(addr));
}
__device__ __forceinline__ void mma16816(float* d, const uint32_t* a, uint32_t b0, uint32_t b1) {
    asm volatile("mma.sync.aligned.m16n8k16.row.col.f32.f16.f16.f32 "
                 "{%0,%1,%2,%3}, {%4,%5,%6,%7}, {%8,%9}, {%0,%1,%2,%3};"
                 : "+f"(d[0]), "+f"(d[1]), "+f"(d[2]), "+f"(d[3])
                 : "r"(a[0]), "r"(a[1]), "r"(a[2]), "r"(a[3]), "r"(b0), "r"(b1));
}
__device__ __forceinline__ float tanh_fast(float x) {
    float y;
    asm("tanh.approx.f32 %0, %1;" : "=f"(y) : "f"(x));
    return y;
}
__device__ __forceinline__ float fast_sig(float x) {
    return __fdividef(1.f, 1.f + __expf(-x));
}
__device__ __forceinline__ float ref_tanh(float x) {
    float e = __expf(2.f * x);
    return 1.f - __fdividef(2.f, e + 1.f);
}
__device__ __forceinline__ float wred(float v) {
    v += __shfl_xor_sync(~0u, v, 16); v += __shfl_xor_sync(~0u, v, 8);
    v += __shfl_xor_sync(~0u, v, 4);  v += __shfl_xor_sync(~0u, v, 2);
    v += __shfl_xor_sync(~0u, v, 1);  return v;
}
__device__ __forceinline__ float qred(float v) {
    v += __shfl_xor_sync(~0u, v, 1);
    v += __shfl_xor_sync(~0u, v, 2);
    v += __shfl_xor_sync(~0u, v, 4);
    return v;
}

// -------- prep: Ua -> fp16 [n][LD] row-major, zero-padded --------
__global__ void prep_ua(const float* __restrict__ Ua) {
    int n = blockIdx.x, k = threadIdx.x;
    if (k < LD) {
        float v = (n < H_ && k < H_) ? Ua[n * H_ + k] : 0.f;
        g_Ua[n * LD + k] = __float2half(v);
    }
}

// -------- prep: qadd --------
__global__ void prep_q(const float* __restrict__ h0, const float* __restrict__ Wa,
                       const float* __restrict__ ba, const float* __restrict__ bua) {
    int b = blockIdx.x, tid = threadIdx.x, wid = tid >> 5, lid = tid & 31;
    __shared__ float hs[H_];
    if (tid < H_) hs[tid] = h0[b * H_ + tid];
    __syncthreads();
    for (int r = wid; r < HP; r += 8) {
        float acc = 0.f;
        if (r < H_) {
            const float* w = Wa + r * H_;
            #pragma unroll
            for (int k = lid; k < H_; k += 32) acc += hs[k] * w[k];
        }
        acc = wred(acc);
        if (lid == 0) g_qadd[b * HP + r] = (r < H_) ? acc + ba[r] + bua[r] : 0.f;
    }
}

// -------- prep: h_pre --------
__global__ void prep_h(const float* __restrict__ h0, const float* __restrict__ Whh,
                       const float* __restrict__ bhh) {
    int b = blockIdx.x, tid = threadIdx.x, wid = tid >> 5, lid = tid & 31;
    __shared__ float hs[H_];
    if (tid < H_) hs[tid] = h0[b * H_ + tid];
    __syncthreads();
    for (int r = wid; r < G4; r += 8) {
        const float* w = Whh + r * H_;
        float acc = 0.f;
        #pragma unroll
        for (int k = lid; k < H_; k += 32) acc += hs[k] * w[k];
        acc = wred(acc);
        if (lid == 0) g_hpre[b * G4 + r] = acc + bhh[r];
    }
}

// -------- scores: two-phase smem + N-split -> 3 CTAs/SM --------
#define SMREG   55296
#define SM_QV2  SMREG
#define SM2_TOT (SMREG + HP * 8 + 64)     // 57024 B

__global__ void __launch_bounds__(256, 3) scores_k(const float* __restrict__ enc,
                                                   const float* __restrict__ Va,
                                                   const float* __restrict__ bva) {
    extern __shared__ char sm[];
    half*   Reg = (half*)sm;
    float2* qv  = (float2*)(sm + SM_QV2);

    int tid = threadIdx.x, wid = tid >> 5, lid = tid & 31;
    int bidx = blockIdx.x;
    int nh = bidx & 1;
    int tt = (bidx >> 1) & 15;
    int b  = bidx >> 5;
    int t0 = tt << 7;
    int n0 = nh ? 112 : 0;
    int np = nh ? 6 : 7;

    const float* encb = enc + (size_t)(b * T_ + t0) * H_;
    for (int u = tid; u < 128 * 27; u += 256) {
        int row = u / 27, oc = u % 27, k = oc * 8;
        uint4 v;
        half2* hp = (half2*)&v;
        if (k < H_) {
            const float4 f0 = *(const float4*)(encb + row * H_ + k);
            const float4 f1 = *(const float4*)(encb + row * H_ + k + 4);
            hp[0] = __floats2half2_rn(f0.x, f0.y);
            hp[1] = __floats2half2_rn(f0.z, f0.w);
            hp[2] = __floats2half2_rn(f1.x, f1.y);
            hp[3] = __floats2half2_rn(f1.z, f1.w);
        } else {
            v = make_uint4(0, 0, 0, 0);
        }
        *(uint4*)(Reg + row * LD + k) = v;
    }
    if (tid < HP) qv[tid] = make_float2(g_qadd[b * HP + tid], (tid < H_) ? Va[tid] : 0.f);
    __syncthreads();

    int lr = lid & 7, quad = lid >> 3;
    uint32_t a_base = smem_u32(Reg) + (uint32_t)(((wid * 16) + (quad & 1) * 8 + lr) * LD + (quad >> 1) * 8) * 2u;
    uint32_t afr[13][4];
    #pragma unroll
    for (int s = 0; s < 13; s++) ldsm4(afr[s], a_base + (uint32_t)(s * 32));
    __syncthreads();

    {
        const uint4* s4 = (const uint4*)(g_Ua + n0 * LD);
        uint4* d4 = (uint4*)Reg;
        int cnt = np * 16 * 27;
        for (int i = tid; i < cnt; i += 256) d4[i] = s4[i];
    }
    __syncthreads();

    uint32_t b_base = smem_u32(Reg) + (uint32_t)((((quad >> 1) * 8) + lr) * LD + (quad & 1) * 8) * 2u;
    float pA = 0.f, pB = 0.f;
    int cq = (lid & 3) * 2;

    for (int pl = 0; pl < np; pl++) {
        float a0[4] = {0.f, 0.f, 0.f, 0.f};
        float a1[4] = {0.f, 0.f, 0.f, 0.f};
        float a2[4] = {0.f, 0.f, 0.f, 0.f};
        float a3[4] = {0.f, 0.f, 0.f, 0.f};
        uint32_t bp = b_base + (uint32_t)(pl * 16 * LD * 2);
        #pragma unroll
        for (int s = 0; s < 13; s++) {
            uint32_t bb[4];
            ldsm4(bb, bp + (uint32_t)(s * 32));
            if (s < 7) {
                mma16816(a0, afr[s], bb[0], bb[1]);
                mma16816(a1, afr[s], bb[2], bb[3]);
            } else {
                mma16816(a2, afr[s], bb[0], bb[1]);
                mma16816(a3, afr[s], bb[2], bb[3]);
            }
        }
        int n = n0 + pl * 16 + cq;
        float2 q0 = qv[n],     q1 = qv[n + 1];
        float2 q2 = qv[n + 8], q3 = qv[n + 9];
        pA += q0.y * tanh_fast(q0.x + a0[0] + a2[0]);
        pA += q1.y * tanh_fast(q1.x + a0[1] + a2[1]);
        pB += q0.y * tanh_fast(q0.x + a0[2] + a2[2]);
        pB += q1.y * tanh_fast(q1.x + a0[3] + a2[3]);
        pA += q2.y * tanh_fast(q2.x + a1[0] + a3[0]);
        pA += q3.y * tanh_fast(q3.x + a1[1] + a3[1]);
        pB += q2.y * tanh_fast(q2.x + a1[2] + a3[2]);
        pB += q3.y * tanh_fast(q3.x + a1[3] + a3[3]);
    }

    pA += __shfl_xor_sync(~0u, pA, 1); pA += __shfl_xor_sync(~0u, pA, 2);
    pB += __shfl_xor_sync(~0u, pB, 1); pB += __shfl_xor_sync(~0u, pB, 2);
    if ((lid & 3) == 0) {
        int r = lid >> 2;
        float bv = nh ? 0.f : bva[0];
        float* dst = nh ? g_sc1 : g_sc0;
        dst[b * T_ + t0 + wid * 16 + r]     = pA + bv;
        dst[b * T_ + t0 + wid * 16 + r + 8] = pB + bv;
    }
}

// -------- softmax over T per batch: att = softmax(sc0+sc1), written to g_sc0 --------
__global__ void softmax_k() {
    int b = blockIdx.x, tid = threadIdx.x;
    __shared__ float red[256];
    float* s0 = g_sc0 + b * T_;
    float* s1 = g_sc1 + b * T_;
    float v[8], m = -1e30f;
    #pragma unroll
    for (int i = 0; i < 8; i++) {
        v[i] = s0[tid + i * 256] + s1[tid + i * 256];
        m = fmaxf(m, v[i]);
    }
    red[tid] = m; __syncthreads();
    for (int st = 128; st > 0; st >>= 1) { if (tid < st) red[tid] = fmaxf(red[tid], red[tid + st]); __syncthreads(); }
    m = red[0]; __syncthreads();
    float sum = 0.f;
    #pragma unroll
    for (int i = 0; i < 8; i++) { v[i] = __expf(v[i] - m); sum += v[i]; }
    red[tid] = sum; __syncthreads();
    for (int st = 128; st > 0; st >>= 1) { if (tid < st) red[tid] += red[tid + st]; __syncthreads(); }
    float inv = 1.f / red[0];
    #pragma unroll
    for (int i = 0; i < 8; i++) s0[tid + i * 256] = v[i] * inv;
}

// -------- context partials: 2048 CTAs for full DRAM bandwidth --------
__global__ void context_k(const float* __restrict__ enc) {
    int b = blockIdx.x, s = blockIdx.y, tid = threadIdx.x;
    __shared__ float w[128];
    if (tid < 128) w[tid] = g_sc0[b * T_ + s * 128 + tid];
    __syncthreads();
    if (tid < H_) {
        const float* p = enc + (size_t)(b * T_ + s * 128) * H_ + tid;
        float acc = 0.f;
        #pragma unroll 8
        for (int t = 0; t < 128; t++) acc += w[t] * p[(size_t)t * H_];
        g_ctxp[(s * B_ + b) * H_ + tid] = acc;
    }
}

// -------- decoder: smem-resident weights + quarter-warp GEMVs (shuffle-safe) --------
#define DW1   0
#define DW2   (100 * 200)
#define DW3   (DW2 + 50 * 104)
#define DSM_FLOATS (DW3 + 64)
#define DSM_TOT (DSM_FLOATS * 4)

__global__ void __launch_bounds__(512) decoder_k(
                          const float* __restrict__ x,  const float* __restrict__ c0,
                          const float* __restrict__ Wih, const float* __restrict__ bih,
                          const float* __restrict__ W1, const float* __restrict__ b1,
                          const float* __restrict__ W2, const float* __restrict__ b2,
                          const float* __restrict__ W3, const float* __restrict__ b3,
                          float* __restrict__ out) {
    extern __shared__ float dsm[];
    __shared__ float ctx[H_], gb[G4], wcol[G4], c0s[H_], r0s[H_];
    __shared__ float l1s[100], l2s[52], b1s[100], b2s[52];
    __shared__ float xs, b3s;

    int b = blockIdx.x, tid = threadIdx.x, wid = tid >> 5, lid = tid & 31;
    int q = lid >> 3, kl = lid & 7;

    {
        const float4* s4 = (const float4*)W1;
        float4* d4 = (float4*)(dsm + DW1);
        for (int i = tid; i < 5000; i += 512) d4[i] = s4[i];
    }
    for (int i = tid; i < 5000; i += 512) {
        int r = i / 100, c = i % 100;
        dsm[DW2 + r * 104 + c] = W2[i];
    }
    if (tid < 50)  { dsm[DW3 + tid] = W3[tid]; b2s[tid] = b2[tid]; }
    if (tid < 100) b1s[tid] = b1[tid];
    if (tid < H_) {
        float a = 0.f;
        #pragma unroll
        for (int j = 0; j < 16; j++) a += g_ctxp[(j * B_ + b) * H_ + tid];
        ctx[tid] = a;
        c0s[tid] = c0[b * H_ + tid];
    }
    if (tid == 0) { xs = x[b]; b3s = b3[0]; }
    for (int g = tid; g < G4; g += 512) wcol[g] = Wih[g * 201];
    __syncthreads();

    for (int base = wid * 4; base < G4; base += 64) {
        int g = base + q;
        const float* w = Wih + g * 201 + 1;
        float acc = 0.f;
        #pragma unroll
        for (int k = kl; k < H_; k += 8) acc += ctx[k] * w[k];
        acc = qred(acc);
        if (kl == 0) gb[g] = acc + bih[g] + g_hpre[b * G4 + g];
    }
    __syncthreads();

    float xv = xs;
    for (int st = 0; st < 5; st++) {
        if (tid < H_) {
            float gi = gb[tid]          + xv * wcol[tid];
            float gf = gb[H_ + tid]     + xv * wcol[H_ + tid];
            float gg = gb[2 * H_ + tid] + xv * wcol[2 * H_ + tid];
            float go = gb[3 * H_ + tid] + xv * wcol[3 * H_ + tid];
            float c  = fast_sig(gf) * c0s[tid] + fast_sig(gi) * ref_tanh(gg);
            float h  = fast_sig(go) * ref_tanh(c);
            r0s[tid] = fmaxf(h, 0.f);
        }
        __syncthreads();
        for (int base = wid * 4; base < 100; base += 64) {
            int r = base + q;
            const float* w = dsm + DW1 + r * 200;
            float acc = 0.f;
            #pragma unroll
            for (int k = kl; k < H_; k += 8) acc += r0s[k] * w[k];
            acc = qred(acc);
            if (kl == 0) l1s[r] = fmaxf(acc + b1s[r], 0.f);
        }
        __syncthreads();
        {
            int base = wid * 4;
            if (base < 52) {
                int r = base + q;
                float acc = 0.f;
                if (r < 50) {
                    const float* w = dsm + DW2 + r * 104;
                    #pragma unroll
                    for (int k = kl; k < 100; k += 8) acc += l1s[k] * w[k];
                }
                acc = qred(acc);
                if (kl == 0 && r < 50) l2s[r] = fmaxf(acc + b2s[r], 0.f);
            }
        }
        __syncthreads();
        if (wid == 0) {
            float acc = 0.f;
            #pragma unroll
            for (int k = lid; k < 50; k += 32) acc += l2s[k] * dsm[DW3 + k];
            acc = wred(acc);
            if (lid == 0) { float y = acc + b3s; out[b * 5 + st] = y; xs = y; }
        }
        __syncthreads();
        xv = xs;
    }
}

extern "C" void kernel_launch(void* const* d_in, const int* in_sizes, int n_in,
                              void* d_out, int out_size) {
    const float* x   = (const float*)d_in[0];
    const float* h0  = (const float*)d_in[1];
    const float* c0  = (const float*)d_in[2];
    const float* enc = (const float*)d_in[3];
    const float* Wa  = (const float*)d_in[4];
    const float* ba  = (const float*)d_in[5];
    const float* Ua  = (const float*)d_in[6];
    const float* bua = (const float*)d_in[7];
    const float* Va  = (const float*)d_in[8];
    const float* bva = (const float*)d_in[9];
    const float* Wih = (const float*)d_in[10];
    const float* Whh = (const float*)d_in[11];
    const float* bih = (const float*)d_in[12];
    const float* bhh = (const float*)d_in[13];
    const float* W1  = (const float*)d_in[14];
    const float* b1  = (const float*)d_in[15];
    const float* W2  = (const float*)d_in[16];
    const float* b2  = (const float*)d_in[17];
    const float* W3  = (const float*)d_in[18];
    const float* b3  = (const float*)d_in[19];
    float* out = (float*)d_out;

    // Uniform smem carveout across ALL kernels -> no per-node SM reconfiguration
    cudaFuncSetAttribute(prep_ua,   cudaFuncAttributePreferredSharedMemoryCarveout, 100);
    cudaFuncSetAttribute(prep_q,    cudaFuncAttributePreferredSharedMemoryCarveout, 100);
    cudaFuncSetAttribute(prep_h,    cudaFuncAttributePreferredSharedMemoryCarveout, 100);
    cudaFuncSetAttribute(scores_k,  cudaFuncAttributePreferredSharedMemoryCarveout, 100);
    cudaFuncSetAttribute(softmax_k, cudaFuncAttributePreferredSharedMemoryCarveout, 100);
    cudaFuncSetAttribute(context_k, cudaFuncAttributePreferredSharedMemoryCarveout, 100);
    cudaFuncSetAttribute(decoder_k, cudaFuncAttributePreferredSharedMemoryCarveout, 100);
    cudaFuncSetAttribute(scores_k,  cudaFuncAttributeMaxDynamicSharedMemorySize, SM2_TOT);
    cudaFuncSetAttribute(decoder_k, cudaFuncAttributeMaxDynamicSharedMemorySize, DSM_TOT);

    prep_ua<<<HP, 256>>>(Ua);                                  // launch 1
    prep_q<<<B_, 256>>>(h0, Wa, ba, bua);                      // launch 2
    prep_h<<<B_, 256>>>(h0, Whh, bhh);                         // launch 3
    scores_k<<<B_ * 32, 256, SM2_TOT>>>(enc, Va, bva);         // launch 4 <- profiled
    softmax_k<<<B_, 256>>>();                                  // launch 5
    context_k<<<dim3(B_, 16), 256>>>(enc);                     // launch 6
    decoder_k<<<B_, 512, DSM_TOT>>>(x, c0, Wih, bih, W1, b1, W2, b2, W3, b3, out);  // launch 7
}

// round 14
// speedup vs baseline: 3.0823x; 1.1878x over previous
#include <cuda_runtime.h>
#include <cuda_fp16.h>
#include <cstdint>

#define B_  128
#define T_  2048
#define H_  200
#define HP  208
#define LD  216
#define G4  800

// ---------------- device scratch ----------------
__device__ __align__(16) half g_Ua[HP * LD];
__device__ float g_qadd[B_ * HP];
__device__ float g_hpre[B_ * G4];
__device__ float g_sc0[B_ * T_];               // scores partial n-half 0 (+bva) -> att (normalized)
__device__ float g_sc1[B_ * T_];               // scores partial n-half 1
__device__ float g_ctxp[16 * B_ * H_];         // context partials
__device__ float g_ctx[B_ * H_];               // final context
__device__ float g_gb[B_ * G4];                // gates base

// ---------------- helpers ----------------
__device__ __forceinline__ uint32_t smem_u32(const void* p) {
    uint32_t a;
    asm("{ .reg .u64 t; cvta.to.shared.u64 t, %1; cvt.u32.u64 %0, t; }" : "=r"(a) : "l"(p));
    return a;
}
__device__ __forceinline__ void ldsm4(uint32_t* r, uint32_t addr) {
    asm volatile("ldmatrix.sync.aligned.m8n8.x4.shared.b16 {%0,%1,%2,%3}, [%4];"
                 : "=r"(r[0]), "=r"(r[1]), "=r"(r[2]), "=r"(r[3]) : "r"(addr));
}
__device__ __forceinline__ void mma16816(float* d, const uint32_t* a, uint32_t b0, uint32_t b1) {
    asm volatile("mma.sync.aligned.m16n8k16.row.col.f32.f16.f16.f32 "
                 "{%0,%1,%2,%3}, {%4,%5,%6,%7}, {%8,%9}, {%0,%1,%2,%3};"
                 : "+f"(d[0]), "+f"(d[1]), "+f"(d[2]), "+f"(d[3])
                 : "r"(a[0]), "r"(a[1]), "r"(a[2]), "r"(a[3]), "r"(b0), "r"(b1));
}
__device__ __forceinline__ float tanh_fast(float x) {
    float y;
    asm("tanh.approx.f32 %0, %1;" : "=f"(y) : "f"(x));
    return y;
}
__device__ __forceinline__ float fast_sig(float x) {
    return __fdividef(1.f, 1.f + __expf(-x));
}
__device__ __forceinline__ float ref_tanh(float x) {
    float e = __expf(2.f * x);
    return 1.f - __fdividef(2.f, e + 1.f);
}
__device__ __forceinline__ float wred(float v) {
    v += __shfl_xor_sync(~0u, v, 16); v += __shfl_xor_sync(~0u, v, 8);
    v += __shfl_xor_sync(~0u, v, 4);  v += __shfl_xor_sync(~0u, v, 2);
    v += __shfl_xor_sync(~0u, v, 1);  return v;
}
__device__ __forceinline__ float qred(float v) {
    v += __shfl_xor_sync(~0u, v, 1);
    v += __shfl_xor_sync(~0u, v, 2);
    v += __shfl_xor_sync(~0u, v, 4);
    return v;
}

// -------- prep (merged): blocks 0..207 lay out Ua; blocks 208..335 do qadd+h_pre --------
__global__ void __launch_bounds__(512) prep_k(const float* __restrict__ Ua,
                                              const float* __restrict__ h0,
                                              const float* __restrict__ Wa,
                                              const float* __restrict__ ba,
                                              const float* __restrict__ bua,
                                              const float* __restrict__ Whh,
                                              const float* __restrict__ bhh) {
    int blk = blockIdx.x, tid = threadIdx.x;
    if (blk < HP) {
        int n = blk;
        if (tid < LD) {
            float v = (n < H_ && tid < H_) ? Ua[n * H_ + tid] : 0.f;
            g_Ua[n * LD + tid] = __float2half(v);
        }
        return;
    }
    int b = blk - HP, wid = tid >> 5, lid = tid & 31;
    __shared__ float hs[H_];
    if (tid < H_) hs[tid] = h0[b * H_ + tid];
    __syncthreads();
    for (int r = wid; r < HP; r += 16) {
        float acc = 0.f;
        if (r < H_) {
            const float* w = Wa + r * H_;
            #pragma unroll
            for (int k = lid; k < H_; k += 32) acc += hs[k] * w[k];
        }
        acc = wred(acc);
        if (lid == 0) g_qadd[b * HP + r] = (r < H_) ? acc + ba[r] + bua[r] : 0.f;
    }
    for (int r = wid; r < G4; r += 16) {
        const float* w = Whh + r * H_;
        float acc = 0.f;
        #pragma unroll
        for (int k = lid; k < H_; k += 32) acc += hs[k] * w[k];
        acc = wred(acc);
        if (lid == 0) g_hpre[b * G4 + r] = acc + bhh[r];
    }
}

// -------- scores: two-phase smem + N-split -> 3 CTAs/SM --------
#define SMREG   55296
#define SM_QV2  SMREG
#define SM2_TOT (SMREG + HP * 8 + 64)

__global__ void __launch_bounds__(256, 3) scores_k(const float* __restrict__ enc,
                                                   const float* __restrict__ Va,
                                                   const float* __restrict__ bva) {
    extern __shared__ char sm[];
    half*   Reg = (half*)sm;
    float2* qv  = (float2*)(sm + SM_QV2);

    int tid = threadIdx.x, wid = tid >> 5, lid = tid & 31;
    int bidx = blockIdx.x;
    int nh = bidx & 1;
    int tt = (bidx >> 1) & 15;
    int b  = bidx >> 5;
    int t0 = tt << 7;
    int n0 = nh ? 112 : 0;
    int np = nh ? 6 : 7;

    const float* encb = enc + (size_t)(b * T_ + t0) * H_;
    for (int u = tid; u < 128 * 27; u += 256) {
        int row = u / 27, oc = u % 27, k = oc * 8;
        uint4 v;
        half2* hp = (half2*)&v;
        if (k < H_) {
            const float4 f0 = *(const float4*)(encb + row * H_ + k);
            const float4 f1 = *(const float4*)(encb + row * H_ + k + 4);
            hp[0] = __floats2half2_rn(f0.x, f0.y);
            hp[1] = __floats2half2_rn(f0.z, f0.w);
            hp[2] = __floats2half2_rn(f1.x, f1.y);
            hp[3] = __floats2half2_rn(f1.z, f1.w);
        } else {
            v = make_uint4(0, 0, 0, 0);
        }
        *(uint4*)(Reg + row * LD + k) = v;
    }
    if (tid < HP) qv[tid] = make_float2(g_qadd[b * HP + tid], (tid < H_) ? Va[tid] : 0.f);
    __syncthreads();

    int lr = lid & 7, quad = lid >> 3;
    uint32_t a_base = smem_u32(Reg) + (uint32_t)(((wid * 16) + (quad & 1) * 8 + lr) * LD + (quad >> 1) * 8) * 2u;
    uint32_t afr[13][4];
    #pragma unroll
    for (int s = 0; s < 13; s++) ldsm4(afr[s], a_base + (uint32_t)(s * 32));
    __syncthreads();

    {
        const uint4* s4 = (const uint4*)(g_Ua + n0 * LD);
        uint4* d4 = (uint4*)Reg;
        int cnt = np * 16 * 27;
        for (int i = tid; i < cnt; i += 256) d4[i] = s4[i];
    }
    __syncthreads();

    uint32_t b_base = smem_u32(Reg) + (uint32_t)((((quad >> 1) * 8) + lr) * LD + (quad & 1) * 8) * 2u;
    float pA = 0.f, pB = 0.f;
    int cq = (lid & 3) * 2;

    for (int pl = 0; pl < np; pl++) {
        float a0[4] = {0.f, 0.f, 0.f, 0.f};
        float a1[4] = {0.f, 0.f, 0.f, 0.f};
        float a2[4] = {0.f, 0.f, 0.f, 0.f};
        float a3[4] = {0.f, 0.f, 0.f, 0.f};
        uint32_t bp = b_base + (uint32_t)(pl * 16 * LD * 2);
        #pragma unroll
        for (int s = 0; s < 13; s++) {
            uint32_t bb[4];
            ldsm4(bb, bp + (uint32_t)(s * 32));
            if (s < 7) {
                mma16816(a0, afr[s], bb[0], bb[1]);
                mma16816(a1, afr[s], bb[2], bb[3]);
            } else {
                mma16816(a2, afr[s], bb[0], bb[1]);
                mma16816(a3, afr[s], bb[2], bb[3]);
            }
        }
        int n = n0 + pl * 16 + cq;
        float2 q0 = qv[n],     q1 = qv[n + 1];
        float2 q2 = qv[n + 8], q3 = qv[n + 9];
        pA += q0.y * tanh_fast(q0.x + a0[0] + a2[0]);
        pA += q1.y * tanh_fast(q1.x + a0[1] + a2[1]);
        pB += q0.y * tanh_fast(q0.x + a0[2] + a2[2]);
        pB += q1.y * tanh_fast(q1.x + a0[3] + a2[3]);
        pA += q2.y * tanh_fast(q2.x + a1[0] + a3[0]);
        pA += q3.y * tanh_fast(q3.x + a1[1] + a3[1]);
        pB += q2.y * tanh_fast(q2.x + a1[2] + a3[2]);
        pB += q3.y * tanh_fast(q3.x + a1[3] + a3[3]);
    }

    pA += __shfl_xor_sync(~0u, pA, 1); pA += __shfl_xor_sync(~0u, pA, 2);
    pB += __shfl_xor_sync(~0u, pB, 1); pB += __shfl_xor_sync(~0u, pB, 2);
    if ((lid & 3) == 0) {
        int r = lid >> 2;
        float bv = nh ? 0.f : bva[0];
        float* dst = nh ? g_sc1 : g_sc0;
        dst[b * T_ + t0 + wid * 16 + r]     = pA + bv;
        dst[b * T_ + t0 + wid * 16 + r + 8] = pB + bv;
    }
}

// -------- softmax over T per batch: att = softmax(sc0+sc1) -> g_sc0 --------
__global__ void softmax_k() {
    int b = blockIdx.x, tid = threadIdx.x;
    __shared__ float red[256];
    float* s0 = g_sc0 + b * T_;
    float* s1 = g_sc1 + b * T_;
    float v[8], m = -1e30f;
    #pragma unroll
    for (int i = 0; i < 8; i++) {
        v[i] = s0[tid + i * 256] + s1[tid + i * 256];
        m = fmaxf(m, v[i]);
    }
    red[tid] = m; __syncthreads();
    for (int st = 128; st > 0; st >>= 1) { if (tid < st) red[tid] = fmaxf(red[tid], red[tid + st]); __syncthreads(); }
    m = red[0]; __syncthreads();
    float sum = 0.f;
    #pragma unroll
    for (int i = 0; i < 8; i++) { v[i] = __expf(v[i] - m); sum += v[i]; }
    red[tid] = sum; __syncthreads();
    for (int st = 128; st > 0; st >>= 1) { if (tid < st) red[tid] += red[tid + st]; __syncthreads(); }
    float inv = 1.f / red[0];
    #pragma unroll
    for (int i = 0; i < 8; i++) s0[tid + i * 256] = v[i] * inv;
}

// -------- context partials: 2048 CTAs for full DRAM bandwidth --------
__global__ void context_k(const float* __restrict__ enc) {
    int b = blockIdx.x, s = blockIdx.y, tid = threadIdx.x;
    __shared__ float w[128];
    if (tid < 128) w[tid] = g_sc0[b * T_ + s * 128 + tid];
    __syncthreads();
    if (tid < H_) {
        const float* p = enc + (size_t)(b * T_ + s * 128) * H_ + tid;
        float acc = 0.f;
        #pragma unroll 8
        for (int t = 0; t < 128; t++) acc += w[t] * p[(size_t)t * H_];
        g_ctxp[(s * B_ + b) * H_ + tid] = acc;
    }
}

// -------- gates base: 1024 CTAs (128 b x 8 slices of 100 rows) --------
__global__ void __launch_bounds__(256) gates_k(const float* __restrict__ Wih,
                                               const float* __restrict__ bih) {
    int b = blockIdx.x, slice = blockIdx.y;
    int tid = threadIdx.x, wid = tid >> 5, lid = tid & 31;
    __shared__ float ctx[H_];
    if (tid < H_) {
        float a = 0.f;
        #pragma unroll
        for (int j = 0; j < 16; j++) a += g_ctxp[(j * B_ + b) * H_ + tid];
        ctx[tid] = a;
        if (slice == 0) g_ctx[b * H_ + tid] = a;
    }
    __syncthreads();
    int g0 = slice * 100;
    for (int r = wid; r < 100; r += 8) {
        int g = g0 + r;
        const float* w = Wih + (size_t)g * 201 + 1;
        float acc = 0.f;
        #pragma unroll
        for (int k = lid; k < H_; k += 32) acc += ctx[k] * w[k];
        acc = wred(acc);
        if (lid == 0) g_gb[b * G4 + g] = acc + bih[g] + g_hpre[b * G4 + g];
    }
}

// -------- decoder: 5 steps only, weights in smem, gates base precomputed --------
#define DW1   0
#define DW2   (100 * 200)
#define DW3   (DW2 + 50 * 104)
#define DSM_FLOATS (DW3 + 64)
#define DSM_TOT (DSM_FLOATS * 4)

__global__ void __launch_bounds__(512) decoder_k(
                          const float* __restrict__ x,  const float* __restrict__ c0,
                          const float* __restrict__ Wih,
                          const float* __restrict__ W1, const float* __restrict__ b1,
                          const float* __restrict__ W2, const float* __restrict__ b2,
                          const float* __restrict__ W3, const float* __restrict__ b3,
                          float* __restrict__ out) {
    extern __shared__ float dsm[];
    __shared__ float gb[G4], wcol[G4], c0s[H_], r0s[H_];
    __shared__ float l1s[100], l2s[52], b1s[100], b2s[52];
    __shared__ float xs, b3s;

    int b = blockIdx.x, tid = threadIdx.x, wid = tid >> 5, lid = tid & 31;
    int q = lid >> 3, kl = lid & 7;

    {
        const float4* s4 = (const float4*)W1;
        float4* d4 = (float4*)(dsm + DW1);
        for (int i = tid; i < 5000; i += 512) d4[i] = s4[i];
    }
    for (int i = tid; i < 5000; i += 512) {
        int r = i / 100, c = i % 100;
        dsm[DW2 + r * 104 + c] = W2[i];
    }
    if (tid < 50)  { dsm[DW3 + tid] = W3[tid]; b2s[tid] = b2[tid]; }
    if (tid < 100) b1s[tid] = b1[tid];
    if (tid < H_) c0s[tid] = c0[b * H_ + tid];
    if (tid == 0) { xs = x[b]; b3s = b3[0]; }
    for (int g = tid; g < G4; g += 512) {
        gb[g]   = g_gb[b * G4 + g];
        wcol[g] = Wih[g * 201];
    }
    __syncthreads();

    float xv = xs;
    for (int st = 0; st < 5; st++) {
        if (tid < H_) {
            float gi = gb[tid]          + xv * wcol[tid];
            float gf = gb[H_ + tid]     + xv * wcol[H_ + tid];
            float gg = gb[2 * H_ + tid] + xv * wcol[2 * H_ + tid];
            float go = gb[3 * H_ + tid] + xv * wcol[3 * H_ + tid];
            float c  = fast_sig(gf) * c0s[tid] + fast_sig(gi) * ref_tanh(gg);
            float h  = fast_sig(go) * ref_tanh(c);
            r0s[tid] = fmaxf(h, 0.f);
        }
        __syncthreads();
        for (int base = wid * 4; base < 100; base += 64) {
            int r = base + q;
            const float* w = dsm + DW1 + r * 200;
            float acc = 0.f;
            #pragma unroll
            for (int k = kl; k < H_; k += 8) acc += r0s[k] * w[k];
            acc = qred(acc);
            if (kl == 0) l1s[r] = fmaxf(acc + b1s[r], 0.f);
        }
        __syncthreads();
        {
            int base = wid * 4;
            if (base < 52) {
                int r = base + q;
                float acc = 0.f;
                if (r < 50) {
                    const float* w = dsm + DW2 + r * 104;
                    #pragma unroll
                    for (int k = kl; k < 100; k += 8) acc += l1s[k] * w[k];
                }
                acc = qred(acc);
                if (kl == 0 && r < 50) l2s[r] = fmaxf(acc + b2s[r], 0.f);
            }
        }
        __syncthreads();
        if (wid == 0) {
            float acc = 0.f;
            #pragma unroll
            for (int k = lid; k < 50; k += 32) acc += l2s[k] * dsm[DW3 + k];
            acc = wred(acc);
            if (lid == 0) { float y = acc + b3s; out[b * 5 + st] = y; xs = y; }
        }
        __syncthreads();
        xv = xs;
    }
}

extern "C" void kernel_launch(void* const* d_in, const int* in_sizes, int n_in,
                              void* d_out, int out_size) {
    const float* x   = (const float*)d_in[0];
    const float* h0  = (const float*)d_in[1];
    const float* c0  = (const float*)d_in[2];
    const float* enc = (const float*)d_in[3];
    const float* Wa  = (const float*)d_in[4];
    const float* ba  = (const float*)d_in[5];
    const float* Ua  = (const float*)d_in[6];
    const float* bua = (const float*)d_in[7];
    const float* Va  = (const float*)d_in[8];
    const float* bva = (const float*)d_in[9];
    const float* Wih = (const float*)d_in[10];
    const float* Whh = (const float*)d_in[11];
    const float* bih = (const float*)d_in[12];
    const float* bhh = (const float*)d_in[13];
    const float* W1  = (const float*)d_in[14];
    const float* b1  = (const float*)d_in[15];
    const float* W2  = (const float*)d_in[16];
    const float* b2  = (const float*)d_in[17];
    const float* W3  = (const float*)d_in[18];
    const float* b3  = (const float*)d_in[19];
    float* out = (float*)d_out;

    // Uniform smem carveout across ALL kernels -> no per-node SM reconfiguration
    cudaFuncSetAttribute(prep_k,    cudaFuncAttributePreferredSharedMemoryCarveout, 100);
    cudaFuncSetAttribute(scores_k,  cudaFuncAttributePreferredSharedMemoryCarveout, 100);
    cudaFuncSetAttribute(softmax_k, cudaFuncAttributePreferredSharedMemoryCarveout, 100);
    cudaFuncSetAttribute(context_k, cudaFuncAttributePreferredSharedMemoryCarveout, 100);
    cudaFuncSetAttribute(gates_k,   cudaFuncAttributePreferredSharedMemoryCarveout, 100);
    cudaFuncSetAttribute(decoder_k, cudaFuncAttributePreferredSharedMemoryCarveout, 100);
    cudaFuncSetAttribute(scores_k,  cudaFuncAttributeMaxDynamicSharedMemorySize, SM2_TOT);
    cudaFuncSetAttribute(decoder_k, cudaFuncAttributeMaxDynamicSharedMemorySize, DSM_TOT);

    prep_k<<<HP + B_, 512>>>(Ua, h0, Wa, ba, bua, Whh, bhh);   // launch 1
    scores_k<<<B_ * 32, 256, SM2_TOT>>>(enc, Va, bva);         // launch 2
    softmax_k<<<B_, 256>>>();                                  // launch 3
    context_k<<<dim3(B_, 16), 256>>>(enc);                     // launch 4 <- profiled
    gates_k<<<dim3(B_, 8), 256>>>(Wih, bih);                   // launch 5
    decoder_k<<<B_, 512, DSM_TOT>>>(x, c0, Wih, W1, b1, W2, b2, W3, b3, out);  // launch 6
}

// round 15
// speedup vs baseline: 3.1783x; 1.0311x over previous
#include <cuda_runtime.h>
#include <cuda_fp16.h>
#include <cstdint>

#define B_  128
#define T_  2048
#define H_  200
#define HP  208
#define LD  216
#define G4  800

// ---------------- device scratch ----------------
__device__ __align__(16) half g_Ua[HP * LD];
__device__ float g_qadd[B_ * HP];
__device__ float g_hpre[B_ * G4];
__device__ float g_sc0[B_ * T_];               // scores partial n-half 0 (+bva)
__device__ float g_sc1[B_ * T_];               // scores partial n-half 1
__device__ float g_ctxp[16 * B_ * H_];         // context partials
__device__ float g_ctx[B_ * H_];               // final context
__device__ float g_gb[B_ * G4];                // gates base

// ---------------- helpers ----------------
__device__ __forceinline__ uint32_t smem_u32(const void* p) {
    uint32_t a;
    asm("{ .reg .u64 t; cvta.to.shared.u64 t, %1; cvt.u32.u64 %0, t; }" : "=r"(a) : "l"(p));
    return a;
}
__device__ __forceinline__ void ldsm4(uint32_t* r, uint32_t addr) {
    asm volatile("ldmatrix.sync.aligned.m8n8.x4.shared.b16 {%0,%1,%2,%3}, [%4];"
                 : "=r"(r[0]), "=r"(r[1]), "=r"(r[2]), "=r"(r[3]) : "r"(addr));
}
__device__ __forceinline__ void mma16816(float* d, const uint32_t* a, uint32_t b0, uint32_t b1) {
    asm volatile("mma.sync.aligned.m16n8k16.row.col.f32.f16.f16.f32 "
                 "{%0,%1,%2,%3}, {%4,%5,%6,%7}, {%8,%9}, {%0,%1,%2,%3};"
                 : "+f"(d[0]), "+f"(d[1]), "+f"(d[2]), "+f"(d[3])
                 : "r"(a[0]), "r"(a[1]), "r"(a[2]), "r"(a[3]), "r"(b0), "r"(b1));
}
__device__ __forceinline__ float tanh_fast(float x) {
    float y;
    asm("tanh.approx.f32 %0, %1;" : "=f"(y) : "f"(x));
    return y;
}
__device__ __forceinline__ float fast_sig(float x) {
    return __fdividef(1.f, 1.f + __expf(-x));
}
__device__ __forceinline__ float ref_tanh(float x) {
    float e = __expf(2.f * x);
    return 1.f - __fdividef(2.f, e + 1.f);
}
__device__ __forceinline__ float wred(float v) {
    v += __shfl_xor_sync(~0u, v, 16); v += __shfl_xor_sync(~0u, v, 8);
    v += __shfl_xor_sync(~0u, v, 4);  v += __shfl_xor_sync(~0u, v, 2);
    v += __shfl_xor_sync(~0u, v, 1);  return v;
}
__device__ __forceinline__ float qred(float v) {
    v += __shfl_xor_sync(~0u, v, 1);
    v += __shfl_xor_sync(~0u, v, 2);
    v += __shfl_xor_sync(~0u, v, 4);
    return v;
}

// -------- prep: Ua -> fp16 [n][LD] row-major, zero-padded --------
__global__ void prep_ua(const float* __restrict__ Ua) {
    int n = blockIdx.x, k = threadIdx.x;
    if (k < LD) {
        float v = (n < H_ && k < H_) ? Ua[n * H_ + k] : 0.f;
        g_Ua[n * LD + k] = __float2half(v);
    }
}

// -------- prep: qadd + h_pre (512 threads, 16 warps) --------
__global__ void __launch_bounds__(512) prep_qh(const float* __restrict__ h0,
                                               const float* __restrict__ Wa,
                                               const float* __restrict__ ba,
                                               const float* __restrict__ bua,
                                               const float* __restrict__ Whh,
                                               const float* __restrict__ bhh) {
    int b = blockIdx.x, tid = threadIdx.x, wid = tid >> 5, lid = tid & 31;
    __shared__ float hs[H_];
    if (tid < H_) hs[tid] = h0[b * H_ + tid];
    __syncthreads();
    for (int r = wid; r < HP; r += 16) {
        float acc = 0.f;
        if (r < H_) {
            const float* w = Wa + r * H_;
            #pragma unroll
            for (int k = lid; k < H_; k += 32) acc += hs[k] * w[k];
        }
        acc = wred(acc);
        if (lid == 0) g_qadd[b * HP + r] = (r < H_) ? acc + ba[r] + bua[r] : 0.f;
    }
    for (int r = wid; r < G4; r += 16) {
        const float* w = Whh + r * H_;
        float acc = 0.f;
        #pragma unroll
        for (int k = lid; k < H_; k += 32) acc += hs[k] * w[k];
        acc = wred(acc);
        if (lid == 0) g_hpre[b * G4 + r] = acc + bhh[r];
    }
}

// -------- scores: two-phase smem + N-split -> 3 CTAs/SM --------
#define SMREG   55296
#define SM_QV2  SMREG
#define SM2_TOT (SMREG + HP * 8 + 64)

__global__ void __launch_bounds__(256, 3) scores_k(const float* __restrict__ enc,
                                                   const float* __restrict__ Va,
                                                   const float* __restrict__ bva) {
    extern __shared__ char sm[];
    half*   Reg = (half*)sm;
    float2* qv  = (float2*)(sm + SM_QV2);

    int tid = threadIdx.x, wid = tid >> 5, lid = tid & 31;
    int bidx = blockIdx.x;
    int nh = bidx & 1;
    int tt = (bidx >> 1) & 15;
    int b  = bidx >> 5;
    int t0 = tt << 7;
    int n0 = nh ? 112 : 0;
    int np = nh ? 6 : 7;

    const float* encb = enc + (size_t)(b * T_ + t0) * H_;
    for (int u = tid; u < 128 * 27; u += 256) {
        int row = u / 27, oc = u % 27, k = oc * 8;
        uint4 v;
        half2* hp = (half2*)&v;
        if (k < H_) {
            const float4 f0 = *(const float4*)(encb + row * H_ + k);
            const float4 f1 = *(const float4*)(encb + row * H_ + k + 4);
            hp[0] = __floats2half2_rn(f0.x, f0.y);
            hp[1] = __floats2half2_rn(f0.z, f0.w);
            hp[2] = __floats2half2_rn(f1.x, f1.y);
            hp[3] = __floats2half2_rn(f1.z, f1.w);
        } else {
            v = make_uint4(0, 0, 0, 0);
        }
        *(uint4*)(Reg + row * LD + k) = v;
    }
    if (tid < HP) qv[tid] = make_float2(g_qadd[b * HP + tid], (tid < H_) ? Va[tid] : 0.f);
    __syncthreads();

    int lr = lid & 7, quad = lid >> 3;
    uint32_t a_base = smem_u32(Reg) + (uint32_t)(((wid * 16) + (quad & 1) * 8 + lr) * LD + (quad >> 1) * 8) * 2u;
    uint32_t afr[13][4];
    #pragma unroll
    for (int s = 0; s < 13; s++) ldsm4(afr[s], a_base + (uint32_t)(s * 32));
    __syncthreads();

    {
        const uint4* s4 = (const uint4*)(g_Ua + n0 * LD);
        uint4* d4 = (uint4*)Reg;
        int cnt = np * 16 * 27;
        for (int i = tid; i < cnt; i += 256) d4[i] = s4[i];
    }
    __syncthreads();

    uint32_t b_base = smem_u32(Reg) + (uint32_t)((((quad >> 1) * 8) + lr) * LD + (quad & 1) * 8) * 2u;
    float pA = 0.f, pB = 0.f;
    int cq = (lid & 3) * 2;

    for (int pl = 0; pl < np; pl++) {
        float a0[4] = {0.f, 0.f, 0.f, 0.f};
        float a1[4] = {0.f, 0.f, 0.f, 0.f};
        float a2[4] = {0.f, 0.f, 0.f, 0.f};
        float a3[4] = {0.f, 0.f, 0.f, 0.f};
        uint32_t bp = b_base + (uint32_t)(pl * 16 * LD * 2);
        #pragma unroll
        for (int s = 0; s < 13; s++) {
            uint32_t bb[4];
            ldsm4(bb, bp + (uint32_t)(s * 32));
            if (s < 7) {
                mma16816(a0, afr[s], bb[0], bb[1]);
                mma16816(a1, afr[s], bb[2], bb[3]);
            } else {
                mma16816(a2, afr[s], bb[0], bb[1]);
                mma16816(a3, afr[s], bb[2], bb[3]);
            }
        }
        int n = n0 + pl * 16 + cq;
        float2 q0 = qv[n],     q1 = qv[n + 1];
        float2 q2 = qv[n + 8], q3 = qv[n + 9];
        pA += q0.y * tanh_fast(q0.x + a0[0] + a2[0]);
        pA += q1.y * tanh_fast(q1.x + a0[1] + a2[1]);
        pB += q0.y * tanh_fast(q0.x + a0[2] + a2[2]);
        pB += q1.y * tanh_fast(q1.x + a0[3] + a2[3]);
        pA += q2.y * tanh_fast(q2.x + a1[0] + a3[0]);
        pA += q3.y * tanh_fast(q3.x + a1[1] + a3[1]);
        pB += q2.y * tanh_fast(q2.x + a1[2] + a3[2]);
        pB += q3.y * tanh_fast(q3.x + a1[3] + a3[3]);
    }

    pA += __shfl_xor_sync(~0u, pA, 1); pA += __shfl_xor_sync(~0u, pA, 2);
    pB += __shfl_xor_sync(~0u, pB, 1); pB += __shfl_xor_sync(~0u, pB, 2);
    if ((lid & 3) == 0) {
        int r = lid >> 2;
        float bv = nh ? 0.f : bva[0];
        float* dst = nh ? g_sc1 : g_sc0;
        dst[b * T_ + t0 + wid * 16 + r]     = pA + bv;
        dst[b * T_ + t0 + wid * 16 + r + 8] = pB + bv;
    }
}

// -------- fused softmax + context partials --------
// grid (128, 16), 512 threads. Each CTA redundantly computes softmax stats over
// the full T (reads sc0+sc1 from L2), normalizes its own 128-t chunk, then two
// 256-thread halves each accumulate 64 t-rows -> halved FFMA chains, 2x MLP.
__global__ void __launch_bounds__(512) sctx_k(const float* __restrict__ enc) {
    __shared__ float att[128];
    __shared__ float part[2][H_];
    __shared__ float redm[16], reds[16], sinv;

    int b = blockIdx.x, s = blockIdx.y;
    int tid = threadIdx.x, wid = tid >> 5, lid = tid & 31;

    // softmax stats over all T (each thread holds 4 values)
    float v[4], m = -1e30f;
    #pragma unroll
    for (int i = 0; i < 4; i++) {
        int idx = tid + i * 512;
        v[i] = g_sc0[b * T_ + idx] + g_sc1[b * T_ + idx];
        m = fmaxf(m, v[i]);
    }
    #pragma unroll
    for (int st = 16; st; st >>= 1) m = fmaxf(m, __shfl_xor_sync(~0u, m, st));
    if (lid == 0) redm[wid] = m;
    __syncthreads();
    if (tid < 32) {
        float mm = (lid < 16) ? redm[lid] : -1e30f;
        #pragma unroll
        for (int st = 8; st; st >>= 1) mm = fmaxf(mm, __shfl_xor_sync(~0u, mm, st));
        if (lid == 0) redm[0] = mm;
    }
    __syncthreads();
    m = redm[0];

    float sum = 0.f;
    #pragma unroll
    for (int i = 0; i < 4; i++) { v[i] = __expf(v[i] - m); sum += v[i]; }
    #pragma unroll
    for (int st = 16; st; st >>= 1) sum += __shfl_xor_sync(~0u, sum, st);
    if (lid == 0) reds[wid] = sum;
    __syncthreads();
    if (tid < 32) {
        float ss = (lid < 16) ? reds[lid] : 0.f;
        #pragma unroll
        for (int st = 8; st; st >>= 1) ss += __shfl_xor_sync(~0u, ss, st);
        if (lid == 0) sinv = 1.f / ss;
    }
    __syncthreads();
    // write this CTA's normalized 128-t chunk
    #pragma unroll
    for (int i = 0; i < 4; i++) {
        int idx = tid + i * 512;
        if ((idx >> 7) == s) att[idx & 127] = v[i] * sinv;
    }
    __syncthreads();

    // context: two halves of 64 t-rows each
    int half = tid >> 8, th = tid & 255;
    if (th < H_) {
        const float* p = enc + ((size_t)(b * T_ + s * 128 + half * 64)) * H_ + th;
        float acc = 0.f;
        const float* aw = att + half * 64;
        #pragma unroll 8
        for (int t = 0; t < 64; t++) acc += aw[t] * p[(size_t)t * H_];
        part[half][th] = acc;
    }
    __syncthreads();
    if (tid < H_)
        g_ctxp[(s * B_ + b) * H_ + tid] = part[0][tid] + part[1][tid];
}

// -------- gates base: 1024 CTAs (128 b x 8 slices of 100 rows) --------
__global__ void __launch_bounds__(256) gates_k(const float* __restrict__ Wih,
                                               const float* __restrict__ bih) {
    int b = blockIdx.x, slice = blockIdx.y;
    int tid = threadIdx.x, wid = tid >> 5, lid = tid & 31;
    __shared__ float ctx[H_];
    if (tid < H_) {
        float a = 0.f;
        #pragma unroll
        for (int j = 0; j < 16; j++) a += g_ctxp[(j * B_ + b) * H_ + tid];
        ctx[tid] = a;
        if (slice == 0) g_ctx[b * H_ + tid] = a;
    }
    __syncthreads();
    int g0 = slice * 100;
    for (int r = wid; r < 100; r += 8) {
        int g = g0 + r;
        const float* w = Wih + (size_t)g * 201 + 1;
        float acc = 0.f;
        #pragma unroll
        for (int k = lid; k < H_; k += 32) acc += ctx[k] * w[k];
        acc = wred(acc);
        if (lid == 0) g_gb[b * G4 + g] = acc + bih[g] + g_hpre[b * G4 + g];
    }
}

// -------- decoder: 5 steps only, weights in smem, gates base precomputed --------
#define DW1   0
#define DW2   (100 * 200)
#define DW3   (DW2 + 50 * 104)
#define DSM_FLOATS (DW3 + 64)
#define DSM_TOT (DSM_FLOATS * 4)

__global__ void __launch_bounds__(512) decoder_k(
                          const float* __restrict__ x,  const float* __restrict__ c0,
                          const float* __restrict__ Wih,
                          const float* __restrict__ W1, const float* __restrict__ b1,
                          const float* __restrict__ W2, const float* __restrict__ b2,
                          const float* __restrict__ W3, const float* __restrict__ b3,
                          float* __restrict__ out) {
    extern __shared__ float dsm[];
    __shared__ float gb[G4], wcol[G4], c0s[H_], r0s[H_];
    __shared__ float l1s[100], l2s[52], b1s[100], b2s[52];
    __shared__ float xs, b3s;

    int b = blockIdx.x, tid = threadIdx.x, wid = tid >> 5, lid = tid & 31;
    int q = lid >> 3, kl = lid & 7;

    {
        const float4* s4 = (const float4*)W1;
        float4* d4 = (float4*)(dsm + DW1);
        for (int i = tid; i < 5000; i += 512) d4[i] = s4[i];
    }
    for (int i = tid; i < 5000; i += 512) {
        int r = i / 100, c = i % 100;
        dsm[DW2 + r * 104 + c] = W2[i];
    }
    if (tid < 50)  { dsm[DW3 + tid] = W3[tid]; b2s[tid] = b2[tid]; }
    if (tid < 100) b1s[tid] = b1[tid];
    if (tid < H_) c0s[tid] = c0[b * H_ + tid];
    if (tid == 0) { xs = x[b]; b3s = b3[0]; }
    for (int g = tid; g < G4; g += 512) {
        gb[g]   = g_gb[b * G4 + g];
        wcol[g] = Wih[g * 201];
    }
    __syncthreads();

    float xv = xs;
    for (int st = 0; st < 5; st++) {
        if (tid < H_) {
            float gi = gb[tid]          + xv * wcol[tid];
            float gf = gb[H_ + tid]     + xv * wcol[H_ + tid];
            float gg = gb[2 * H_ + tid] + xv * wcol[2 * H_ + tid];
            float go = gb[3 * H_ + tid] + xv * wcol[3 * H_ + tid];
            float c  = fast_sig(gf) * c0s[tid] + fast_sig(gi) * ref_tanh(gg);
            float h  = fast_sig(go) * ref_tanh(c);
            r0s[tid] = fmaxf(h, 0.f);
        }
        __syncthreads();
        for (int base = wid * 4; base < 100; base += 64) {
            int r = base + q;
            const float* w = dsm + DW1 + r * 200;
            float acc = 0.f;
            #pragma unroll
            for (int k = kl; k < H_; k += 8) acc += r0s[k] * w[k];
            acc = qred(acc);
            if (kl == 0) l1s[r] = fmaxf(acc + b1s[r], 0.f);
        }
        __syncthreads();
        {
            int base = wid * 4;
            if (base < 52) {
                int r = base + q;
                float acc = 0.f;
                if (r < 50) {
                    const float* w = dsm + DW2 + r * 104;
                    #pragma unroll
                    for (int k = kl; k < 100; k += 8) acc += l1s[k] * w[k];
                }
                acc = qred(acc);
                if (kl == 0 && r < 50) l2s[r] = fmaxf(acc + b2s[r], 0.f);
            }
        }
        __syncthreads();
        if (wid == 0) {
            float acc = 0.f;
            #pragma unroll
            for (int k = lid; k < 50; k += 32) acc += l2s[k] * dsm[DW3 + k];
            acc = wred(acc);
            if (lid == 0) { float y = acc + b3s; out[b * 5 + st] = y; xs = y; }
        }
        __syncthreads();
        xv = xs;
    }
}

extern "C" void kernel_launch(void* const* d_in, const int* in_sizes, int n_in,
                              void* d_out, int out_size) {
    const float* x   = (const float*)d_in[0];
    const float* h0  = (const float*)d_in[1];
    const float* c0  = (const float*)d_in[2];
    const float* enc = (const float*)d_in[3];
    const float* Wa  = (const float*)d_in[4];
    const float* ba  = (const float*)d_in[5];
    const float* Ua  = (const float*)d_in[6];
    const float* bua = (const float*)d_in[7];
    const float* Va  = (const float*)d_in[8];
    const float* bva = (const float*)d_in[9];
    const float* Wih = (const float*)d_in[10];
    const float* Whh = (const float*)d_in[11];
    const float* bih = (const float*)d_in[12];
    const float* bhh = (const float*)d_in[13];
    const float* W1  = (const float*)d_in[14];
    const float* b1  = (const float*)d_in[15];
    const float* W2  = (const float*)d_in[16];
    const float* b2  = (const float*)d_in[17];
    const float* W3  = (const float*)d_in[18];
    const float* b3  = (const float*)d_in[19];
    float* out = (float*)d_out;

    // Uniform smem carveout across ALL kernels -> no per-node SM reconfiguration
    cudaFuncSetAttribute(prep_ua,   cudaFuncAttributePreferredSharedMemoryCarveout, 100);
    cudaFuncSetAttribute(prep_qh,   cudaFuncAttributePreferredSharedMemoryCarveout, 100);
    cudaFuncSetAttribute(scores_k,  cudaFuncAttributePreferredSharedMemoryCarveout, 100);
    cudaFuncSetAttribute(sctx_k,    cudaFuncAttributePreferredSharedMemoryCarveout, 100);
    cudaFuncSetAttribute(gates_k,   cudaFuncAttributePreferredSharedMemoryCarveout, 100);
    cudaFuncSetAttribute(decoder_k, cudaFuncAttributePreferredSharedMemoryCarveout, 100);
    cudaFuncSetAttribute(scores_k,  cudaFuncAttributeMaxDynamicSharedMemorySize, SM2_TOT);
    cudaFuncSetAttribute(decoder_k, cudaFuncAttributeMaxDynamicSharedMemorySize, DSM_TOT);

    prep_ua<<<HP, 256>>>(Ua);                                  // launch 1
    prep_qh<<<B_, 512>>>(h0, Wa, ba, bua, Whh, bhh);           // launch 2
    scores_k<<<B_ * 32, 256, SM2_TOT>>>(enc, Va, bva);         // launch 3
    sctx_k<<<dim3(B_, 16), 512>>>(enc);                        // launch 4 <- profiled
    gates_k<<<dim3(B_, 8), 256>>>(Wih, bih);                   // launch 5
    decoder_k<<<B_, 512, DSM_TOT>>>(x, c0, Wih, W1, b1, W2, b2, W3, b3, out);  // launch 6
}